// round 11
// baseline (speedup 1.0000x reference)
#include <cuda_runtime.h>
#include <cuda_bf16.h>
#include <math.h>
#include <stdint.h>

typedef unsigned long long ull;

#define BATCH 64
#define LSEQ  2048
#define DMODEL 256
#define DU 1024
#define HHID 128
#define NTOK (BATCH*LSEQ)
#define LTOK 64
#define NT2 (NTOK/LTOK)   // 2048

// ---------------- device scratch ----------------
__device__ __nv_bfloat16 g_hev_hi[(size_t)NTOK * DMODEL];
__device__ __nv_bfloat16 g_hev_lo[(size_t)NTOK * DMODEL];
__device__ __nv_bfloat16 g_Wa_hi[DU * DMODEL];
__device__ __nv_bfloat16 g_Wa_lo[DU * DMODEL];
__device__ __nv_bfloat16 g_W1_hi[HHID * DMODEL];
__device__ __nv_bfloat16 g_W1_lo[HHID * DMODEL];
__device__ float g_cvec[HHID];
__device__ float g_aval[NTOK];
__device__ int   g_active[NTOK];
__device__ int   g_count[BATCH];
__device__ int   g_tile;

// ---------------- helpers ----------------
__device__ __forceinline__ float lrelu(float x) { return x > 0.f ? x : 0.2f * x; }

__device__ __forceinline__ uint32_t smem_u32(const void* p) {
    uint32_t a;
    asm("{ .reg .u64 t; cvta.to.shared.u64 t, %1; cvt.u32.u64 %0, t; }" : "=r"(a) : "l"(p));
    return a;
}
__device__ __forceinline__ void mma16816(float* d, const uint32_t* a, const uint32_t* b) {
    asm volatile(
        "mma.sync.aligned.m16n8k16.row.col.f32.bf16.bf16.f32 "
        "{%0,%1,%2,%3}, {%4,%5,%6,%7}, {%8,%9}, {%0,%1,%2,%3};"
        : "+f"(d[0]), "+f"(d[1]), "+f"(d[2]), "+f"(d[3])
        : "r"(a[0]), "r"(a[1]), "r"(a[2]), "r"(a[3]), "r"(b[0]), "r"(b[1]));
}
__device__ __forceinline__ void ldsm4(uint32_t* r, uint32_t addr) {
    asm volatile("ldmatrix.sync.aligned.m8n8.x4.shared.b16 {%0,%1,%2,%3}, [%4];"
        : "=r"(r[0]), "=r"(r[1]), "=r"(r[2]), "=r"(r[3]) : "r"(addr));
}
__device__ __forceinline__ void cp16(uint32_t dst, const void* src) {
    asm volatile("cp.async.cg.shared.global [%0], [%1], 16;" :: "r"(dst), "l"(src));
}
#define CP_COMMIT() asm volatile("cp.async.commit_group;" ::: "memory")
#define CP_WAIT0()  asm volatile("cp.async.wait_group 0;" ::: "memory")

__device__ __forceinline__ uint32_t pack_bf16x2(float lo, float hi) {
    __nv_bfloat162 p = __floats2bfloat162_rn(lo, hi);
    uint32_t u; memcpy(&u, &p, 4); return u;
}

// ---------------- kernel 0a: constant head bias ----------------
__global__ void k_setup(const float* __restrict__ Ws1, const float* __restrict__ bs1,
                        const float* __restrict__ vn) {
    int h = blockIdx.x * (blockDim.x >> 5) + (threadIdx.x >> 5);
    int l = threadIdx.x & 31;
    if (h >= HHID) return;
    const float* row = Ws1 + (size_t)h * 512 + 256;
    float s = 0.f;
#pragma unroll
    for (int d = l; d < 256; d += 32) s += row[d] * vn[d];
#pragma unroll
    for (int off = 16; off; off >>= 1) s += __shfl_xor_sync(0xffffffffu, s, off);
    if (l == 0) g_cvec[h] = s + bs1[h];
}

// ---------------- kernel 0b: weights -> bf16 hi/lo, zero outputs ----------------
__global__ void k_prep(const float* __restrict__ Wa, const float* __restrict__ Ws1,
                       float* __restrict__ out_u) {
    int idx = blockIdx.x * blockDim.x + threadIdx.x;
    if (idx < DU * DMODEL) {
        float v = Wa[idx];
        __nv_bfloat16 hi = __float2bfloat16(v);
        __nv_bfloat16 lo = __float2bfloat16(v - __bfloat162float(hi));
        g_Wa_hi[idx] = hi;
        g_Wa_lo[idx] = lo;
    }
    if (idx < HHID * DMODEL) {
        int h = idx >> 8, d = idx & 255;
        float v = Ws1[h * 512 + d];
        __nv_bfloat16 hi = __float2bfloat16(v);
        __nv_bfloat16 lo = __float2bfloat16(v - __bfloat162float(hi));
        g_W1_hi[idx] = hi;
        g_W1_lo[idx] = lo;
    }
    if (idx < BATCH * DU) out_u[idx] = 0.f;
    if (idx < BATCH) g_count[idx] = 0;
    if (idx == 0) g_tile = 0;
}

// ---------------- kernel 1: FUSED embed + HMMA logits + compaction ----------------
// 512 thr, persistent. Phase A builds the 64-token h tile (gather+trig) directly
// into GEMM staging smem (bf16 hi/lo) and writes g_hev once. GEMM + epilogue as R10.
// smem: sW[2][128][528B]@0 (135168), sH[2 halves][2 terms][64][272B]@135168 (69632),
//       slog[4][64]@204800, sq/sr/st@205824, stile@206600
#define LW_OFF   0
#define LW_TERM  67584
#define LH_OFF   135168
#define LH_BUF   34816
#define LH_TERM  17408
#define LSLOG    204800
#define LSEQ_OFF 205824
#define LSTILE   206656
#define SMEM_LG  206720

__global__ __launch_bounds__(512, 1) void k_logits_fused(
    const int* __restrict__ q_seq, const int* __restrict__ r_seq,
    const float* __restrict__ t_seq, const float* __restrict__ mask,
    const float* __restrict__ q_tab, const float* __restrict__ r_tab,
    const float* __restrict__ Ws2, const float* __restrict__ bs2,
    float* __restrict__ outA)
{
    extern __shared__ char smem[];
    const uint32_t sb = smem_u32(smem);
    const int tid  = threadIdx.x;
    const int wid  = tid >> 5;
    const int lane = tid & 31;
    const int gid  = lane >> 2;
    const int warpM = wid >> 2;       // 0..3 -> 32-h groups
    const int warpN = wid & 3;        // 0..3 -> 16-token groups

    float* slog  = (float*)(smem + LSLOG);
    int*   sq    = (int*)(smem + LSEQ_OFF);          // 64
    int*   sr    = sq + 64;                          // 64
    float* stv   = (float*)(sr + 64);                // 64
    int*   stile = (int*)(smem + LSTILE);

    // stage Ws1a hi/lo once per block
    for (int i = tid; i < 8192; i += 512) {
        int term = i >> 12;
        int r = (i >> 5) & 127;
        int c = i & 31;
        const __nv_bfloat16* src = term ? g_W1_lo : g_W1_hi;
        uint4 v = ((const uint4*)(src + ((size_t)r << 8)))[c];
        *(uint4*)(smem + LW_OFF + term * LW_TERM + r * 528 + c * 16) = v;
    }

    // epilogue constants (2 m-tiles of 16 h)
    float wc[2][2], cv[2][2];
#pragma unroll
    for (int m = 0; m < 2; ++m) {
        int h0 = warpM * 32 + m * 16 + gid;
        wc[m][0] = Ws2[h0];     wc[m][1] = Ws2[h0 + 8];
        cv[m][0] = g_cvec[h0];  cv[m][1] = g_cvec[h0 + 8];
    }
    const float b2v = bs2[0];

    // phase-A per-thread constants: d0 = 2*(tid&127), tokens [16*tseg, 16*tseg+16)
    const int dp   = tid & 127;
    const int tseg = tid >> 7;         // 0..3
    const int d0   = dp * 2;
    const int half = d0 >> 7;
    const int dd   = d0 & 127;
    const float KF = -9.2103403719761836f / 128.f;
    const float f0 = expf((float)(d0 & 127) * KF);
    const float f1 = expf((float)((d0 + 1) & 127) * KF);
    const bool  is_sin = d0 < 128;
    const uint32_t sm_hi = sb + LH_OFF + (uint32_t)(half * LH_BUF + dd * 2);
    const uint32_t sm_lo = sm_hi + LH_TERM;

    const uint32_t w_ld = sb + LW_OFF + (uint32_t)((lane & 15) * 528 + (lane >> 4) * 16);
    const uint32_t h_ld = sb + LH_OFF +
        (uint32_t)((warpN * 16 + (lane & 15)) * 272 + (lane >> 4) * 16);

    if (tid == 0) *stile = atomicAdd(&g_tile, 1);
    __syncthreads();
    int tile = *stile;

    while (tile < NT2) {
        const int tok0 = tile * LTOK;
        const int b    = tok0 >> 11;

        if (tid < 64) {
            sq[tid]  = q_seq[tok0 + tid];
            sr[tid]  = r_seq[tok0 + tid];
            stv[tid] = t_seq[tok0 + tid];
        }
        __syncthreads();

        // ---- Phase A: build h tile into smem (bf16 hi/lo) + g_hev ----
        {
            uint32_t* ghw = (uint32_t*)(g_hev_hi + (((size_t)tok0 + tseg * 16) << 8) + d0);
            uint32_t* glw = (uint32_t*)(g_hev_lo + (((size_t)tok0 + tseg * 16) << 8) + d0);
#pragma unroll 2
            for (int t = 0; t < 16; ++t) {
                int tok = tseg * 16 + t;
                float tv = stv[tok];
                float a0 = tv * f0, a1 = tv * f1;
                float s0 = is_sin ? sinf(a0) : cosf(a0);
                float s1 = is_sin ? sinf(a1) : cosf(a1);
                const float2 q2 = *(const float2*)(q_tab + (size_t)sq[tok] * 256 + d0);
                const float2 r2 = *(const float2*)(r_tab + (size_t)sr[tok] * 256 + d0);
                float v0 = q2.x + r2.x + s0;
                float v1 = q2.y + r2.y + s1;
                float h0f = __bfloat162float(__float2bfloat16(v0));
                float h1f = __bfloat162float(__float2bfloat16(v1));
                uint32_t whi = pack_bf16x2(h0f, h1f);
                uint32_t wlo = pack_bf16x2(v0 - h0f, v1 - h1f);
                uint32_t soff = (uint32_t)(tok * 272);
                asm volatile("st.shared.b32 [%0], %1;" :: "r"(sm_hi + soff), "r"(whi));
                asm volatile("st.shared.b32 [%0], %1;" :: "r"(sm_lo + soff), "r"(wlo));
                ghw[(size_t)t << 7] = whi;
                glw[(size_t)t << 7] = wlo;
            }
        }
        if (tid == 0) *stile = atomicAdd(&g_tile, 1);
        __syncthreads();

        float C[2][2][4];
#pragma unroll
        for (int m = 0; m < 2; ++m)
#pragma unroll
            for (int n = 0; n < 2; ++n)
#pragma unroll
                for (int k = 0; k < 4; ++k) C[m][n][k] = 0.f;

        // ---- GEMM: both K-halves, no intermediate sync ----
#pragma unroll
        for (int kh = 0; kh < 2; ++kh) {
#pragma unroll
            for (int ks = 0; ks < 8; ++ks) {
                uint32_t ah[2][4], al[2][4], bh[2][2], bl[2][2], tmp[4];
#pragma unroll
                for (int m = 0; m < 2; ++m) {
                    uint32_t ro = (uint32_t)((warpM * 32 + m * 16) * 528 + (kh * 8 + ks) * 32);
                    ldsm4(ah[m], w_ld + ro);
                    ldsm4(al[m], w_ld + LW_TERM + ro);
                }
                {
                    uint32_t no = (uint32_t)(kh * LH_BUF + ks * 32);
                    ldsm4(tmp, h_ld + no);
                    bh[0][0] = tmp[0]; bh[1][0] = tmp[1];
                    bh[0][1] = tmp[2]; bh[1][1] = tmp[3];
                    ldsm4(tmp, h_ld + LH_TERM + no);
                    bl[0][0] = tmp[0]; bl[1][0] = tmp[1];
                    bl[0][1] = tmp[2]; bl[1][1] = tmp[3];
                }
#pragma unroll
                for (int m = 0; m < 2; ++m)
#pragma unroll
                    for (int n = 0; n < 2; ++n) mma16816(C[m][n], ah[m], bh[n]);
#pragma unroll
                for (int m = 0; m < 2; ++m)
#pragma unroll
                    for (int n = 0; n < 2; ++n) mma16816(C[m][n], ah[m], bl[n]);
#pragma unroll
                for (int m = 0; m < 2; ++m)
#pragma unroll
                    for (int n = 0; n < 2; ++n) mma16816(C[m][n], al[m], bh[n]);
            }
        }

        // ---- epilogue: hdn -> ws2-weighted token partials ----
        {
            float tsum[2][2];
#pragma unroll
            for (int n = 0; n < 2; ++n) { tsum[n][0] = 0.f; tsum[n][1] = 0.f; }
#pragma unroll
            for (int m = 0; m < 2; ++m)
#pragma unroll
                for (int n = 0; n < 2; ++n) {
                    tsum[n][0] += wc[m][0] * lrelu(C[m][n][0] + cv[m][0])
                                + wc[m][1] * lrelu(C[m][n][2] + cv[m][1]);
                    tsum[n][1] += wc[m][0] * lrelu(C[m][n][1] + cv[m][0])
                                + wc[m][1] * lrelu(C[m][n][3] + cv[m][1]);
                }
#pragma unroll
            for (int n = 0; n < 2; ++n)
#pragma unroll
                for (int k2 = 0; k2 < 2; ++k2) {
                    float v = tsum[n][k2];
                    v += __shfl_xor_sync(0xffffffffu, v, 4);
                    v += __shfl_xor_sync(0xffffffffu, v, 8);
                    v += __shfl_xor_sync(0xffffffffu, v, 16);
                    tsum[n][k2] = v;
                }
            if (lane < 4) {
#pragma unroll
                for (int n = 0; n < 2; ++n) {
                    int t = warpN * 16 + n * 8 + 2 * lane;
                    slog[warpM * 64 + t]     = tsum[n][0];
                    slog[warpM * 64 + t + 1] = tsum[n][1];
                }
            }
        }
        __syncthreads();

        // ---- sigmoid + compaction (2 warps) ----
        if (tid < 64) {
            float logit = slog[tid] + slog[64 + tid] + slog[128 + tid]
                        + slog[192 + tid] + b2v;
            float a = mask[tok0 + tid] / (1.f + expf(-logit * 100.f));
            outA[tok0 + tid]   = a;
            g_aval[tok0 + tid] = a;
            bool act = a > 1e-10f;
            unsigned mb = __ballot_sync(0xffffffffu, act);
            int cntw = __popc(mb);
            int base = 0;
            if (lane == 0 && cntw) base = atomicAdd(&g_count[b], cntw);
            base = __shfl_sync(0xffffffffu, base, 0);
            if (act) {
                int slot = base + __popc(mb & ((1u << lane) - 1u));
                g_active[b * LSEQ + slot] = (tok0 & (LSEQ - 1)) + tid;
            }
        }
        tile = *stile;
        __syncthreads();
    }
}

// ---------------- kernel 2: HMMA aggregator (512 thr, 16 warps, 4 batches/block) ----------------
#define KA_B_OFF   0
#define KA_A_OFF   135168
#define KA_ABUF    34816
#define KA_ATERM   17408
#define KA_SA_OFF  204800
#define KA_STOK_OFF 205312
#define SMEM_AGG   205824

__global__ __launch_bounds__(512, 1) void k_agg_p(const float* __restrict__ ba,
                                                  float* __restrict__ out_u)
{
    extern __shared__ char smem[];
    const uint32_t sb = smem_u32(smem);
    const int tid  = threadIdx.x;
    const int wid  = tid >> 5;
    const int lane = tid & 31;
    const int gid  = lane >> 2;
    const int colbase = blockIdx.x * 128;
    const int warpM = wid >> 2;
    const int warpN = wid & 3;

    float* sa   = (float*)(smem + KA_SA_OFF);
    int*   stok = (int*)(smem + KA_STOK_OFF);

    for (int i = tid; i < 8192; i += 512) {
        int term = i >> 12;
        int r = (i >> 5) & 127;
        int c = i & 31;
        const __nv_bfloat16* src = term ? g_Wa_lo : g_Wa_hi;
        uint4 v = ((const uint4*)(src + ((size_t)(colbase + r) << 8)))[c];
        *(uint4*)(smem + KA_B_OFF + term * 67584 + r * 528 + c * 16) = v;
    }

    float ban0[4], ban1[4];
#pragma unroll
    for (int n = 0; n < 4; ++n) {
        int c0 = colbase + warpN * 32 + n * 8 + 2 * (lane & 3);
        ban0[n] = ba[c0];
        ban1[n] = ba[c0 + 1];
    }

    const uint32_t a_ld_base = sb + KA_A_OFF
        + (uint32_t)((lane & 15) * 272 + (lane >> 4) * 16);
    const uint32_t b_ld_base = sb + KA_B_OFF
        + (uint32_t)((warpN * 32 + (lane & 15)) * 528 + (lane >> 4) * 16);

    for (int bi = 0; bi < 4; ++bi) {
        const int b = blockIdx.y * 4 + bi;
        const int cnt = g_count[b];
        const int ntile = (cnt + 63) >> 6;

        __syncthreads();

        float colacc[4][2];
#pragma unroll
        for (int n = 0; n < 4; ++n) { colacc[n][0] = 0.f; colacc[n][1] = 0.f; }

        if (tid < 64 && ntile > 0) {
            int tok = (tid < cnt) ? g_active[(b << 11) + tid] : 0;
            stok[tid] = tok;
            sa[tid]   = (tid < cnt) ? g_aval[(b << 11) + tok] : 0.f;
        }
        __syncthreads();

        if (ntile > 0) {
#pragma unroll
            for (int i = 0; i < 4; ++i) {
                int idx = tid + i * 512;
                int term = idx >> 10;
                int row  = (idx >> 4) & 63;
                int c    = idx & 15;
                const __nv_bfloat16* src = term ? g_hev_lo : g_hev_hi;
                cp16(sb + KA_A_OFF + (uint32_t)(term * KA_ATERM + row * 272 + c * 16),
                     src + (((size_t)(b << 11) + stok[row]) << 8) + (c << 3));
            }
            CP_COMMIT();
        }

        int cur = 0;
        for (int t = 0; t < ntile; ++t, cur ^= 1) {
            const int nxt = cur ^ 1;
            if (tid < 64 && t + 1 < ntile) {
                int slot = ((t + 1) << 6) + tid;
                int tok = (slot < cnt) ? g_active[(b << 11) + slot] : 0;
                stok[nxt * 64 + tid] = tok;
                sa[nxt * 64 + tid]   = (slot < cnt) ? g_aval[(b << 11) + tok] : 0.f;
            }
            CP_WAIT0();
            __syncthreads();

#pragma unroll
            for (int i = 0; i < 4; ++i) {
                int idx = tid + i * 512;
                int term = idx >> 10;
                int row  = (idx >> 4) & 63;
                int c    = idx & 15;
                const __nv_bfloat16* src = term ? g_hev_lo : g_hev_hi;
                cp16(sb + KA_A_OFF + KA_ABUF
                         + (uint32_t)(term * KA_ATERM + row * 272 + c * 16),
                     src + (((size_t)(b << 11) + stok[cur * 64 + row]) << 8) + 128 + (c << 3));
            }
            CP_COMMIT();

            float C[4][4];
#pragma unroll
            for (int n = 0; n < 4; ++n)
#pragma unroll
                for (int k = 0; k < 4; ++k) C[n][k] = 0.f;

#pragma unroll
            for (int ks = 0; ks < 8; ++ks) {
                uint32_t ah[4], al[4], bh[4][2], bl[4][2], tmp[4];
                {
                    uint32_t ro = (uint32_t)((warpM * 16) * 272 + ks * 32);
                    ldsm4(ah, a_ld_base + ro);
                    ldsm4(al, a_ld_base + KA_ATERM + ro);
                }
#pragma unroll
                for (int nc = 0; nc < 2; ++nc) {
                    uint32_t no = (uint32_t)(nc * 16 * 528 + ks * 32);
                    ldsm4(tmp, b_ld_base + no);
                    bh[2*nc][0] = tmp[0]; bh[2*nc+1][0] = tmp[1];
                    bh[2*nc][1] = tmp[2]; bh[2*nc+1][1] = tmp[3];
                    ldsm4(tmp, b_ld_base + 67584 + no);
                    bl[2*nc][0] = tmp[0]; bl[2*nc+1][0] = tmp[1];
                    bl[2*nc][1] = tmp[2]; bl[2*nc+1][1] = tmp[3];
                }
#pragma unroll
                for (int n = 0; n < 4; ++n) mma16816(C[n], ah, bh[n]);
#pragma unroll
                for (int n = 0; n < 4; ++n) mma16816(C[n], ah, bl[n]);
#pragma unroll
                for (int n = 0; n < 4; ++n) mma16816(C[n], al, bh[n]);
            }

            CP_WAIT0();
            __syncthreads();

            if (t + 1 < ntile) {
#pragma unroll
                for (int i = 0; i < 4; ++i) {
                    int idx = tid + i * 512;
                    int term = idx >> 10;
                    int row  = (idx >> 4) & 63;
                    int c    = idx & 15;
                    const __nv_bfloat16* src = term ? g_hev_lo : g_hev_hi;
                    cp16(sb + KA_A_OFF + (uint32_t)(term * KA_ATERM + row * 272 + c * 16),
                         src + (((size_t)(b << 11) + stok[nxt * 64 + row]) << 8) + (c << 3));
                }
                CP_COMMIT();
            }

#pragma unroll
            for (int ks = 0; ks < 8; ++ks) {
                uint32_t ah[4], al[4], bh[4][2], bl[4][2], tmp[4];
                {
                    uint32_t ro = (uint32_t)((warpM * 16) * 272 + ks * 32);
                    ldsm4(ah, a_ld_base + KA_ABUF + ro);
                    ldsm4(al, a_ld_base + KA_ABUF + KA_ATERM + ro);
                }
#pragma unroll
                for (int nc = 0; nc < 2; ++nc) {
                    uint32_t no = (uint32_t)(nc * 16 * 528 + 256 + ks * 32);
                    ldsm4(tmp, b_ld_base + no);
                    bh[2*nc][0] = tmp[0]; bh[2*nc+1][0] = tmp[1];
                    bh[2*nc][1] = tmp[2]; bh[2*nc+1][1] = tmp[3];
                    ldsm4(tmp, b_ld_base + 67584 + no);
                    bl[2*nc][0] = tmp[0]; bl[2*nc+1][0] = tmp[1];
                    bl[2*nc][1] = tmp[2]; bl[2*nc+1][1] = tmp[3];
                }
#pragma unroll
                for (int n = 0; n < 4; ++n) mma16816(C[n], ah, bh[n]);
#pragma unroll
                for (int n = 0; n < 4; ++n) mma16816(C[n], ah, bl[n]);
#pragma unroll
                for (int n = 0; n < 4; ++n) mma16816(C[n], al, bh[n]);
            }

            {
                float a0 = sa[cur * 64 + warpM * 16 + gid];
                float a1 = sa[cur * 64 + warpM * 16 + gid + 8];
#pragma unroll
                for (int n = 0; n < 4; ++n) {
                    colacc[n][0] += a0 * lrelu(C[n][0] + ban0[n])
                                  + a1 * lrelu(C[n][2] + ban0[n]);
                    colacc[n][1] += a0 * lrelu(C[n][1] + ban1[n])
                                  + a1 * lrelu(C[n][3] + ban1[n]);
                }
            }
        }

#pragma unroll
        for (int n = 0; n < 4; ++n)
#pragma unroll
            for (int j = 0; j < 2; ++j) {
                float v = colacc[n][j];
                v += __shfl_xor_sync(0xffffffffu, v, 4);
                v += __shfl_xor_sync(0xffffffffu, v, 8);
                v += __shfl_xor_sync(0xffffffffu, v, 16);
                colacc[n][j] = v;
            }
        if (lane < 4) {
#pragma unroll
            for (int n = 0; n < 4; ++n) {
                int c0 = colbase + warpN * 32 + n * 8 + 2 * lane;
                atomicAdd(&out_u[b * DU + c0],     colacc[n][0]);
                atomicAdd(&out_u[b * DU + c0 + 1], colacc[n][1]);
            }
        }
    }
}

// ---------------- launch ----------------
extern "C" void kernel_launch(void* const* d_in, const int* in_sizes, int n_in,
                              void* d_out, int out_size) {
    const int*   q_seq = (const int*)d_in[0];
    const int*   r_seq = (const int*)d_in[1];
    const float* t_seq = (const float*)d_in[2];
    const float* mask  = (const float*)d_in[3];
    const float* q_tab = (const float*)d_in[4];
    const float* r_tab = (const float*)d_in[5];
    const float* vn    = (const float*)d_in[6];
    const float* Ws1   = (const float*)d_in[7];
    const float* bs1   = (const float*)d_in[8];
    const float* Ws2   = (const float*)d_in[9];
    const float* bs2   = (const float*)d_in[10];
    const float* Wa    = (const float*)d_in[11];
    const float* ba    = (const float*)d_in[12];

    float* out_u = (float*)d_out;            // (64, 1024)
    float* outA  = out_u + BATCH * DU;       // (64, 2048)

    k_setup<<<4, 1024>>>(Ws1, bs1, vn);
    k_prep<<<(DU * DMODEL + 255) / 256, 256>>>(Wa, Ws1, out_u);

    cudaFuncSetAttribute(k_logits_fused, cudaFuncAttributeMaxDynamicSharedMemorySize, SMEM_LG);
    k_logits_fused<<<148, 512, SMEM_LG>>>(q_seq, r_seq, t_seq, mask,
                                          q_tab, r_tab, Ws2, bs2, outA);

    cudaFuncSetAttribute(k_agg_p, cudaFuncAttributeMaxDynamicSharedMemorySize, SMEM_AGG);
    k_agg_p<<<dim3(8, 16), 512, SMEM_AGG>>>(ba, out_u);
}

// round 12
// speedup vs baseline: 1.2035x; 1.2035x over previous
#include <cuda_runtime.h>
#include <cuda_bf16.h>
#include <math.h>
#include <stdint.h>

typedef unsigned long long ull;

#define BATCH 64
#define LSEQ  2048
#define DMODEL 256
#define DU 1024
#define HHID 128
#define NTOK (BATCH*LSEQ)
#define LTOK 64
#define NT2 (NTOK/LTOK)   // 2048

// ---------------- device scratch ----------------
__device__ __nv_bfloat16 g_hev_hi[(size_t)NTOK * DMODEL];
__device__ __nv_bfloat16 g_hev_lo[(size_t)NTOK * DMODEL];
__device__ __nv_bfloat16 g_Wa_hi[DU * DMODEL];
__device__ __nv_bfloat16 g_Wa_lo[DU * DMODEL];
__device__ __nv_bfloat16 g_W1_hi[HHID * DMODEL];
__device__ __nv_bfloat16 g_W1_lo[HHID * DMODEL];
__device__ float g_cvec[HHID];
__device__ float g_aval[NTOK];
__device__ int   g_active[NTOK];
__device__ int   g_count[BATCH];
__device__ int   g_tile;

// ---------------- helpers ----------------
__device__ __forceinline__ float lrelu(float x) { return x > 0.f ? x : 0.2f * x; }

__device__ __forceinline__ uint32_t smem_u32(const void* p) {
    uint32_t a;
    asm("{ .reg .u64 t; cvta.to.shared.u64 t, %1; cvt.u32.u64 %0, t; }" : "=r"(a) : "l"(p));
    return a;
}
__device__ __forceinline__ void mma16816(float* d, const uint32_t* a, const uint32_t* b) {
    asm volatile(
        "mma.sync.aligned.m16n8k16.row.col.f32.bf16.bf16.f32 "
        "{%0,%1,%2,%3}, {%4,%5,%6,%7}, {%8,%9}, {%0,%1,%2,%3};"
        : "+f"(d[0]), "+f"(d[1]), "+f"(d[2]), "+f"(d[3])
        : "r"(a[0]), "r"(a[1]), "r"(a[2]), "r"(a[3]), "r"(b[0]), "r"(b[1]));
}
__device__ __forceinline__ void ldsm4(uint32_t* r, uint32_t addr) {
    asm volatile("ldmatrix.sync.aligned.m8n8.x4.shared.b16 {%0,%1,%2,%3}, [%4];"
        : "=r"(r[0]), "=r"(r[1]), "=r"(r[2]), "=r"(r[3]) : "r"(addr));
}
__device__ __forceinline__ void cp16(uint32_t dst, const void* src) {
    asm volatile("cp.async.cg.shared.global [%0], [%1], 16;" :: "r"(dst), "l"(src));
}
#define CP_COMMIT() asm volatile("cp.async.commit_group;" ::: "memory")
#define CP_WAIT0()  asm volatile("cp.async.wait_group 0;" ::: "memory")
#define CP_WAIT1()  asm volatile("cp.async.wait_group 1;" ::: "memory")

__device__ __forceinline__ uint32_t pack_bf16x2(float lo, float hi) {
    __nv_bfloat162 p = __floats2bfloat162_rn(lo, hi);
    uint32_t u; memcpy(&u, &p, 4); return u;
}

// ---------------- kernel 0: merged init (prep + setup) ----------------
// blocks [0,1024): Wa/Ws1 bf16 split + zero outputs. blocks [1024,1040): cvec.
__global__ __launch_bounds__(256) void k_init(
    const float* __restrict__ Wa, const float* __restrict__ Ws1,
    const float* __restrict__ bs1, const float* __restrict__ vn,
    float* __restrict__ out_u)
{
    const int bid = blockIdx.x;
    const int tid = threadIdx.x;
    if (bid < 1024) {
        int idx = bid * 256 + tid;
        if (idx < DU * DMODEL) {
            float v = Wa[idx];
            __nv_bfloat16 hi = __float2bfloat16(v);
            __nv_bfloat16 lo = __float2bfloat16(v - __bfloat162float(hi));
            g_Wa_hi[idx] = hi;
            g_Wa_lo[idx] = lo;
        }
        if (idx < HHID * DMODEL) {
            int h = idx >> 8, d = idx & 255;
            float v = Ws1[h * 512 + d];
            __nv_bfloat16 hi = __float2bfloat16(v);
            __nv_bfloat16 lo = __float2bfloat16(v - __bfloat162float(hi));
            g_W1_hi[idx] = hi;
            g_W1_lo[idx] = lo;
        }
        if (idx < BATCH * DU) out_u[idx] = 0.f;
        if (idx < BATCH) g_count[idx] = 0;
        if (idx == 0) g_tile = 0;
    } else {
        int h = (bid - 1024) * 8 + (tid >> 5);   // 16 blocks x 8 warps = 128 h
        int l = tid & 31;
        if (h >= HHID) return;
        const float* row = Ws1 + (size_t)h * 512 + 256;
        float s = 0.f;
#pragma unroll
        for (int d = l; d < 256; d += 32) s += row[d] * vn[d];
#pragma unroll
        for (int off = 16; off; off >>= 1) s += __shfl_xor_sync(0xffffffffu, s, off);
        if (l == 0) g_cvec[h] = s + bs1[h];
    }
}

// ---------------- kernel 1a: embedding + trig -> bf16 hi/lo (vectorized) ----------------
// 256 thr, 32 tokens/block. Thread: d-pair d0=2*(tid&127), 16 tokens (tid>>7 segment).
__global__ __launch_bounds__(256) void k_emb(
    const int* __restrict__ q_seq, const int* __restrict__ r_seq,
    const float* __restrict__ t_seq,
    const float* __restrict__ q_tab, const float* __restrict__ r_tab)
{
    __shared__ int sq[32], sr[32];
    __shared__ float st[32];
    const int tid = threadIdx.x;
    const int tok0 = blockIdx.x * 32;
    if (tid < 32) {
        sq[tid] = q_seq[tok0 + tid];
        sr[tid] = r_seq[tok0 + tid];
        st[tid] = t_seq[tok0 + tid];
    }
    __syncthreads();
    const int dp   = tid & 127;
    const int tseg = tid >> 7;          // 0/1 -> 16 tokens each
    const int d0   = dp * 2;
    const float KF = -9.2103403719761836f / 128.f;
    const float f0 = expf((float)(d0 & 127) * KF);
    const float f1 = expf((float)((d0 + 1) & 127) * KF);
    const bool  is_sin = d0 < 128;
    uint32_t* ghw = (uint32_t*)(g_hev_hi + (((size_t)tok0 + tseg * 16) << 8) + d0);
    uint32_t* glw = (uint32_t*)(g_hev_lo + (((size_t)tok0 + tseg * 16) << 8) + d0);
#pragma unroll 4
    for (int t = 0; t < 16; ++t) {
        int tok = tseg * 16 + t;
        float tv = st[tok];
        float a0 = tv * f0, a1 = tv * f1;
        float s0 = is_sin ? sinf(a0) : cosf(a0);
        float s1 = is_sin ? sinf(a1) : cosf(a1);
        const float2 q2 = *(const float2*)(q_tab + (size_t)sq[tok] * 256 + d0);
        const float2 r2 = *(const float2*)(r_tab + (size_t)sr[tok] * 256 + d0);
        float v0 = q2.x + r2.x + s0;
        float v1 = q2.y + r2.y + s1;
        float h0f = __bfloat162float(__float2bfloat16(v0));
        float h1f = __bfloat162float(__float2bfloat16(v1));
        ghw[(size_t)t << 7] = pack_bf16x2(h0f, h1f);
        glw[(size_t)t << 7] = pack_bf16x2(v0 - h0f, v1 - h1f);
    }
}

// ---------------- kernel 1b: pipelined HMMA logits (512 thr, REVERSED tile order) ----------------
#define LW_OFF   0
#define LW_TERM  67584
#define LH_OFF   135168
#define LH_BUF   34816
#define LH_TERM  17408
#define LSLOG    204800
#define LSTILE   205824
#define SMEM_LG  205952

__global__ __launch_bounds__(512, 1) void k_logits_mma(
    const float* __restrict__ mask, const float* __restrict__ Ws2,
    const float* __restrict__ bs2, float* __restrict__ outA)
{
    extern __shared__ char smem[];
    const uint32_t sb = smem_u32(smem);
    const int tid  = threadIdx.x;
    const int wid  = tid >> 5;
    const int lane = tid & 31;
    const int gid  = lane >> 2;
    const int warpM = wid >> 2;
    const int warpN = wid & 3;

    float* slog  = (float*)(smem + LSLOG);
    int*   stile = (int*)(smem + LSTILE);

    for (int i = tid; i < 8192; i += 512) {
        int term = i >> 12;
        int r = (i >> 5) & 127;
        int c = i & 31;
        const __nv_bfloat16* src = term ? g_W1_lo : g_W1_hi;
        uint4 v = ((const uint4*)(src + ((size_t)r << 8)))[c];
        *(uint4*)(smem + LW_OFF + term * LW_TERM + r * 528 + c * 16) = v;
    }

    float wc[2][2], cv[2][2];
#pragma unroll
    for (int m = 0; m < 2; ++m) {
        int h0 = warpM * 32 + m * 16 + gid;
        wc[m][0] = Ws2[h0];     wc[m][1] = Ws2[h0 + 8];
        cv[m][0] = g_cvec[h0];  cv[m][1] = g_cvec[h0 + 8];
    }
    const float b2v = bs2[0];

    const uint32_t w_ld = sb + LW_OFF + (uint32_t)((lane & 15) * 528 + (lane >> 4) * 16);
    const uint32_t h_ld = sb + LH_OFF +
        (uint32_t)((warpN * 16 + (lane & 15)) * 272 + (lane >> 4) * 16);

    if (tid == 0) *stile = atomicAdd(&g_tile, 1);
    __syncthreads();
    int tctr = *stile;
    int tile = NT2 - 1 - tctr;   // REVERSED: read freshest k_emb output first

    // prologue: issue kh0 -> buf0
    if (tctr < NT2) {
#pragma unroll
        for (int i = 0; i < 4; ++i) {
            int idx = tid + i * 512;
            int term = idx >> 10;
            int row  = (idx >> 4) & 63;
            int c    = idx & 15;
            const __nv_bfloat16* src = term ? g_hev_lo : g_hev_hi;
            cp16(sb + LH_OFF + (uint32_t)(term * LH_TERM + row * 272 + c * 16),
                 src + (((size_t)(tile * LTOK + row)) << 8) + (c << 3));
        }
        CP_COMMIT();
    }

    while (tctr < NT2) {
        const int tok0 = tile * LTOK;
        const int b    = tok0 >> 11;

        // issue kh1 -> buf1
#pragma unroll
        for (int i = 0; i < 4; ++i) {
            int idx = tid + i * 512;
            int term = idx >> 10;
            int row  = (idx >> 4) & 63;
            int c    = idx & 15;
            const __nv_bfloat16* src = term ? g_hev_lo : g_hev_hi;
            cp16(sb + LH_OFF + LH_BUF + (uint32_t)(term * LH_TERM + row * 272 + c * 16),
                 src + (((size_t)(tok0 + row)) << 8) + 128 + (c << 3));
        }
        CP_COMMIT();
        if (tid == 0) *stile = atomicAdd(&g_tile, 1);

        CP_WAIT1();
        __syncthreads();        // buf0 (kh0) ready

        float C[2][2][4];
#pragma unroll
        for (int m = 0; m < 2; ++m)
#pragma unroll
            for (int n = 0; n < 2; ++n)
#pragma unroll
                for (int k = 0; k < 4; ++k) C[m][n][k] = 0.f;

        // ---- GEMM kh0 (buf0) ----
#pragma unroll
        for (int ks = 0; ks < 8; ++ks) {
            uint32_t ah[2][4], al[2][4], bh[2][2], bl[2][2], tmp[4];
#pragma unroll
            for (int m = 0; m < 2; ++m) {
                uint32_t ro = (uint32_t)((warpM * 32 + m * 16) * 528 + ks * 32);
                ldsm4(ah[m], w_ld + ro);
                ldsm4(al[m], w_ld + LW_TERM + ro);
            }
            {
                uint32_t no = (uint32_t)(ks * 32);
                ldsm4(tmp, h_ld + no);
                bh[0][0] = tmp[0]; bh[1][0] = tmp[1];
                bh[0][1] = tmp[2]; bh[1][1] = tmp[3];
                ldsm4(tmp, h_ld + LH_TERM + no);
                bl[0][0] = tmp[0]; bl[1][0] = tmp[1];
                bl[0][1] = tmp[2]; bl[1][1] = tmp[3];
            }
#pragma unroll
            for (int m = 0; m < 2; ++m)
#pragma unroll
                for (int n = 0; n < 2; ++n) mma16816(C[m][n], ah[m], bh[n]);
#pragma unroll
            for (int m = 0; m < 2; ++m)
#pragma unroll
                for (int n = 0; n < 2; ++n) mma16816(C[m][n], ah[m], bl[n]);
#pragma unroll
            for (int m = 0; m < 2; ++m)
#pragma unroll
                for (int n = 0; n < 2; ++n) mma16816(C[m][n], al[m], bh[n]);
        }
        __syncthreads();        // buf0 free

        const int nctr = *stile;
        const int ntile = NT2 - 1 - nctr;
        if (nctr < NT2) {
#pragma unroll
            for (int i = 0; i < 4; ++i) {
                int idx = tid + i * 512;
                int term = idx >> 10;
                int row  = (idx >> 4) & 63;
                int c    = idx & 15;
                const __nv_bfloat16* src = term ? g_hev_lo : g_hev_hi;
                cp16(sb + LH_OFF + (uint32_t)(term * LH_TERM + row * 272 + c * 16),
                     src + (((size_t)(ntile * LTOK + row)) << 8) + (c << 3));
            }
            CP_COMMIT();
            CP_WAIT1();
        } else {
            CP_WAIT0();
        }
        __syncthreads();        // buf1 (kh1) ready

        // ---- GEMM kh1 (buf1) ----
#pragma unroll
        for (int ks = 0; ks < 8; ++ks) {
            uint32_t ah[2][4], al[2][4], bh[2][2], bl[2][2], tmp[4];
#pragma unroll
            for (int m = 0; m < 2; ++m) {
                uint32_t ro = (uint32_t)((warpM * 32 + m * 16) * 528 + (8 + ks) * 32);
                ldsm4(ah[m], w_ld + ro);
                ldsm4(al[m], w_ld + LW_TERM + ro);
            }
            {
                uint32_t no = (uint32_t)(LH_BUF + ks * 32);
                ldsm4(tmp, h_ld + no);
                bh[0][0] = tmp[0]; bh[1][0] = tmp[1];
                bh[0][1] = tmp[2]; bh[1][1] = tmp[3];
                ldsm4(tmp, h_ld + LH_TERM + no);
                bl[0][0] = tmp[0]; bl[1][0] = tmp[1];
                bl[0][1] = tmp[2]; bl[1][1] = tmp[3];
            }
#pragma unroll
            for (int m = 0; m < 2; ++m)
#pragma unroll
                for (int n = 0; n < 2; ++n) mma16816(C[m][n], ah[m], bh[n]);
#pragma unroll
            for (int m = 0; m < 2; ++m)
#pragma unroll
                for (int n = 0; n < 2; ++n) mma16816(C[m][n], ah[m], bl[n]);
#pragma unroll
            for (int m = 0; m < 2; ++m)
#pragma unroll
                for (int n = 0; n < 2; ++n) mma16816(C[m][n], al[m], bh[n]);
        }

        // ---- epilogue ----
        {
            float tsum[2][2];
#pragma unroll
            for (int n = 0; n < 2; ++n) { tsum[n][0] = 0.f; tsum[n][1] = 0.f; }
#pragma unroll
            for (int m = 0; m < 2; ++m)
#pragma unroll
                for (int n = 0; n < 2; ++n) {
                    tsum[n][0] += wc[m][0] * lrelu(C[m][n][0] + cv[m][0])
                                + wc[m][1] * lrelu(C[m][n][2] + cv[m][1]);
                    tsum[n][1] += wc[m][0] * lrelu(C[m][n][1] + cv[m][0])
                                + wc[m][1] * lrelu(C[m][n][3] + cv[m][1]);
                }
#pragma unroll
            for (int n = 0; n < 2; ++n)
#pragma unroll
                for (int k2 = 0; k2 < 2; ++k2) {
                    float v = tsum[n][k2];
                    v += __shfl_xor_sync(0xffffffffu, v, 4);
                    v += __shfl_xor_sync(0xffffffffu, v, 8);
                    v += __shfl_xor_sync(0xffffffffu, v, 16);
                    tsum[n][k2] = v;
                }
            if (lane < 4) {
#pragma unroll
                for (int n = 0; n < 2; ++n) {
                    int t = warpN * 16 + n * 8 + 2 * lane;
                    slog[warpM * 64 + t]     = tsum[n][0];
                    slog[warpM * 64 + t + 1] = tsum[n][1];
                }
            }
        }
        __syncthreads();

        // ---- sigmoid + compaction ----
        if (tid < 64) {
            float logit = slog[tid] + slog[64 + tid] + slog[128 + tid]
                        + slog[192 + tid] + b2v;
            float a = mask[tok0 + tid] / (1.f + expf(-logit * 100.f));
            outA[tok0 + tid]   = a;
            g_aval[tok0 + tid] = a;
            bool act = a > 1e-10f;
            unsigned mb = __ballot_sync(0xffffffffu, act);
            int cntw = __popc(mb);
            int base = 0;
            if (lane == 0 && cntw) base = atomicAdd(&g_count[b], cntw);
            base = __shfl_sync(0xffffffffu, base, 0);
            if (act) {
                int slot = base + __popc(mb & ((1u << lane) - 1u));
                g_active[b * LSEQ + slot] = (tok0 & (LSEQ - 1)) + tid;
            }
        }
        tctr = nctr;
        tile = ntile;
        __syncthreads();
    }
}

// ---------------- kernel 2: HMMA aggregator (512 thr, 4 batches/block) ----------------
#define KA_B_OFF   0
#define KA_A_OFF   135168
#define KA_ABUF    34816
#define KA_ATERM   17408
#define KA_SA_OFF  204800
#define KA_STOK_OFF 205312
#define SMEM_AGG   205824

__global__ __launch_bounds__(512, 1) void k_agg_p(const float* __restrict__ ba,
                                                  float* __restrict__ out_u)
{
    extern __shared__ char smem[];
    const uint32_t sb = smem_u32(smem);
    const int tid  = threadIdx.x;
    const int wid  = tid >> 5;
    const int lane = tid & 31;
    const int gid  = lane >> 2;
    const int colbase = blockIdx.x * 128;
    const int warpM = wid >> 2;
    const int warpN = wid & 3;

    float* sa   = (float*)(smem + KA_SA_OFF);
    int*   stok = (int*)(smem + KA_STOK_OFF);

    for (int i = tid; i < 8192; i += 512) {
        int term = i >> 12;
        int r = (i >> 5) & 127;
        int c = i & 31;
        const __nv_bfloat16* src = term ? g_Wa_lo : g_Wa_hi;
        uint4 v = ((const uint4*)(src + ((size_t)(colbase + r) << 8)))[c];
        *(uint4*)(smem + KA_B_OFF + term * 67584 + r * 528 + c * 16) = v;
    }

    float ban0[4], ban1[4];
#pragma unroll
    for (int n = 0; n < 4; ++n) {
        int c0 = colbase + warpN * 32 + n * 8 + 2 * (lane & 3);
        ban0[n] = ba[c0];
        ban1[n] = ba[c0 + 1];
    }

    const uint32_t a_ld_base = sb + KA_A_OFF
        + (uint32_t)((lane & 15) * 272 + (lane >> 4) * 16);
    const uint32_t b_ld_base = sb + KA_B_OFF
        + (uint32_t)((warpN * 32 + (lane & 15)) * 528 + (lane >> 4) * 16);

    for (int bi = 0; bi < 4; ++bi) {
        const int b = blockIdx.y * 4 + bi;
        const int cnt = g_count[b];
        const int ntile = (cnt + 63) >> 6;

        __syncthreads();

        float colacc[4][2];
#pragma unroll
        for (int n = 0; n < 4; ++n) { colacc[n][0] = 0.f; colacc[n][1] = 0.f; }

        if (tid < 64 && ntile > 0) {
            int tok = (tid < cnt) ? g_active[(b << 11) + tid] : 0;
            stok[tid] = tok;
            sa[tid]   = (tid < cnt) ? g_aval[(b << 11) + tok] : 0.f;
        }
        __syncthreads();

        if (ntile > 0) {
#pragma unroll
            for (int i = 0; i < 4; ++i) {
                int idx = tid + i * 512;
                int term = idx >> 10;
                int row  = (idx >> 4) & 63;
                int c    = idx & 15;
                const __nv_bfloat16* src = term ? g_hev_lo : g_hev_hi;
                cp16(sb + KA_A_OFF + (uint32_t)(term * KA_ATERM + row * 272 + c * 16),
                     src + (((size_t)(b << 11) + stok[row]) << 8) + (c << 3));
            }
            CP_COMMIT();
        }

        int cur = 0;
        for (int t = 0; t < ntile; ++t, cur ^= 1) {
            const int nxt = cur ^ 1;
            if (tid < 64 && t + 1 < ntile) {
                int slot = ((t + 1) << 6) + tid;
                int tok = (slot < cnt) ? g_active[(b << 11) + slot] : 0;
                stok[nxt * 64 + tid] = tok;
                sa[nxt * 64 + tid]   = (slot < cnt) ? g_aval[(b << 11) + tok] : 0.f;
            }
            CP_WAIT0();
            __syncthreads();

#pragma unroll
            for (int i = 0; i < 4; ++i) {
                int idx = tid + i * 512;
                int term = idx >> 10;
                int row  = (idx >> 4) & 63;
                int c    = idx & 15;
                const __nv_bfloat16* src = term ? g_hev_lo : g_hev_hi;
                cp16(sb + KA_A_OFF + KA_ABUF
                         + (uint32_t)(term * KA_ATERM + row * 272 + c * 16),
                     src + (((size_t)(b << 11) + stok[cur * 64 + row]) << 8) + 128 + (c << 3));
            }
            CP_COMMIT();

            float C[4][4];
#pragma unroll
            for (int n = 0; n < 4; ++n)
#pragma unroll
                for (int k = 0; k < 4; ++k) C[n][k] = 0.f;

#pragma unroll
            for (int ks = 0; ks < 8; ++ks) {
                uint32_t ah[4], al[4], bh[4][2], bl[4][2], tmp[4];
                {
                    uint32_t ro = (uint32_t)((warpM * 16) * 272 + ks * 32);
                    ldsm4(ah, a_ld_base + ro);
                    ldsm4(al, a_ld_base + KA_ATERM + ro);
                }
#pragma unroll
                for (int nc = 0; nc < 2; ++nc) {
                    uint32_t no = (uint32_t)(nc * 16 * 528 + ks * 32);
                    ldsm4(tmp, b_ld_base + no);
                    bh[2*nc][0] = tmp[0]; bh[2*nc+1][0] = tmp[1];
                    bh[2*nc][1] = tmp[2]; bh[2*nc+1][1] = tmp[3];
                    ldsm4(tmp, b_ld_base + 67584 + no);
                    bl[2*nc][0] = tmp[0]; bl[2*nc+1][0] = tmp[1];
                    bl[2*nc][1] = tmp[2]; bl[2*nc+1][1] = tmp[3];
                }
#pragma unroll
                for (int n = 0; n < 4; ++n) mma16816(C[n], ah, bh[n]);
#pragma unroll
                for (int n = 0; n < 4; ++n) mma16816(C[n], ah, bl[n]);
#pragma unroll
                for (int n = 0; n < 4; ++n) mma16816(C[n], al, bh[n]);
            }

            CP_WAIT0();
            __syncthreads();

            if (t + 1 < ntile) {
#pragma unroll
                for (int i = 0; i < 4; ++i) {
                    int idx = tid + i * 512;
                    int term = idx >> 10;
                    int row  = (idx >> 4) & 63;
                    int c    = idx & 15;
                    const __nv_bfloat16* src = term ? g_hev_lo : g_hev_hi;
                    cp16(sb + KA_A_OFF + (uint32_t)(term * KA_ATERM + row * 272 + c * 16),
                         src + (((size_t)(b << 11) + stok[nxt * 64 + row]) << 8) + (c << 3));
                }
                CP_COMMIT();
            }

#pragma unroll
            for (int ks = 0; ks < 8; ++ks) {
                uint32_t ah[4], al[4], bh[4][2], bl[4][2], tmp[4];
                {
                    uint32_t ro = (uint32_t)((warpM * 16) * 272 + ks * 32);
                    ldsm4(ah, a_ld_base + KA_ABUF + ro);
                    ldsm4(al, a_ld_base + KA_ABUF + KA_ATERM + ro);
                }
#pragma unroll
                for (int nc = 0; nc < 2; ++nc) {
                    uint32_t no = (uint32_t)(nc * 16 * 528 + 256 + ks * 32);
                    ldsm4(tmp, b_ld_base + no);
                    bh[2*nc][0] = tmp[0]; bh[2*nc+1][0] = tmp[1];
                    bh[2*nc][1] = tmp[2]; bh[2*nc+1][1] = tmp[3];
                    ldsm4(tmp, b_ld_base + 67584 + no);
                    bl[2*nc][0] = tmp[0]; bl[2*nc+1][0] = tmp[1];
                    bl[2*nc][1] = tmp[2]; bl[2*nc+1][1] = tmp[3];
                }
#pragma unroll
                for (int n = 0; n < 4; ++n) mma16816(C[n], ah, bh[n]);
#pragma unroll
                for (int n = 0; n < 4; ++n) mma16816(C[n], ah, bl[n]);
#pragma unroll
                for (int n = 0; n < 4; ++n) mma16816(C[n], al, bh[n]);
            }

            {
                float a0 = sa[cur * 64 + warpM * 16 + gid];
                float a1 = sa[cur * 64 + warpM * 16 + gid + 8];
#pragma unroll
                for (int n = 0; n < 4; ++n) {
                    colacc[n][0] += a0 * lrelu(C[n][0] + ban0[n])
                                  + a1 * lrelu(C[n][2] + ban0[n]);
                    colacc[n][1] += a0 * lrelu(C[n][1] + ban1[n])
                                  + a1 * lrelu(C[n][3] + ban1[n]);
                }
            }
        }

#pragma unroll
        for (int n = 0; n < 4; ++n)
#pragma unroll
            for (int j = 0; j < 2; ++j) {
                float v = colacc[n][j];
                v += __shfl_xor_sync(0xffffffffu, v, 4);
                v += __shfl_xor_sync(0xffffffffu, v, 8);
                v += __shfl_xor_sync(0xffffffffu, v, 16);
                colacc[n][j] = v;
            }
        if (lane < 4) {
#pragma unroll
            for (int n = 0; n < 4; ++n) {
                int c0 = colbase + warpN * 32 + n * 8 + 2 * lane;
                atomicAdd(&out_u[b * DU + c0],     colacc[n][0]);
                atomicAdd(&out_u[b * DU + c0 + 1], colacc[n][1]);
            }
        }
    }
}

// ---------------- launch ----------------
extern "C" void kernel_launch(void* const* d_in, const int* in_sizes, int n_in,
                              void* d_out, int out_size) {
    const int*   q_seq = (const int*)d_in[0];
    const int*   r_seq = (const int*)d_in[1];
    const float* t_seq = (const float*)d_in[2];
    const float* mask  = (const float*)d_in[3];
    const float* q_tab = (const float*)d_in[4];
    const float* r_tab = (const float*)d_in[5];
    const float* vn    = (const float*)d_in[6];
    const float* Ws1   = (const float*)d_in[7];
    const float* bs1   = (const float*)d_in[8];
    const float* Ws2   = (const float*)d_in[9];
    const float* bs2   = (const float*)d_in[10];
    const float* Wa    = (const float*)d_in[11];
    const float* ba    = (const float*)d_in[12];

    float* out_u = (float*)d_out;            // (64, 1024)
    float* outA  = out_u + BATCH * DU;       // (64, 2048)

    k_init<<<1040, 256>>>(Wa, Ws1, bs1, vn, out_u);

    k_emb<<<NTOK / 32, 256>>>(q_seq, r_seq, t_seq, q_tab, r_tab);

    cudaFuncSetAttribute(k_logits_mma, cudaFuncAttributeMaxDynamicSharedMemorySize, SMEM_LG);
    k_logits_mma<<<148, 512, SMEM_LG>>>(mask, Ws2, bs2, outA);

    cudaFuncSetAttribute(k_agg_p, cudaFuncAttributeMaxDynamicSharedMemorySize, SMEM_AGG);
    k_agg_p<<<dim3(8, 16), 512, SMEM_AGG>>>(ba, out_u);
}

// round 14
// speedup vs baseline: 1.2408x; 1.0310x over previous
#include <cuda_runtime.h>
#include <cuda_bf16.h>
#include <math.h>
#include <stdint.h>

typedef unsigned long long ull;

#define BATCH 64
#define LSEQ  2048
#define DMODEL 256
#define DU 1024
#define HHID 128
#define NTOK (BATCH*LSEQ)
#define LTOK 64
#define NT2 (NTOK/LTOK)   // 2048

// ---------------- device scratch ----------------
__device__ __nv_bfloat16 g_hev_hi[(size_t)NTOK * DMODEL];
__device__ __nv_bfloat16 g_hev_lo[(size_t)NTOK * DMODEL];
__device__ __nv_bfloat16 g_Wa_hi[DU * DMODEL];
__device__ __nv_bfloat16 g_Wa_lo[DU * DMODEL];
__device__ __nv_bfloat16 g_W1_hi[HHID * DMODEL];
__device__ __nv_bfloat16 g_W1_lo[HHID * DMODEL];
__device__ float g_cvec[HHID];
__device__ float g_aval[NTOK];
__device__ int   g_active[NTOK];
__device__ int   g_count[BATCH];
__device__ int   g_tile;
__device__ int   g_work;

// ---------------- helpers ----------------
__device__ __forceinline__ float lrelu(float x) { return x > 0.f ? x : 0.2f * x; }

__device__ __forceinline__ uint32_t smem_u32(const void* p) {
    uint32_t a;
    asm("{ .reg .u64 t; cvta.to.shared.u64 t, %1; cvt.u32.u64 %0, t; }" : "=r"(a) : "l"(p));
    return a;
}
__device__ __forceinline__ void mma16816(float* d, const uint32_t* a, const uint32_t* b) {
    asm volatile(
        "mma.sync.aligned.m16n8k16.row.col.f32.bf16.bf16.f32 "
        "{%0,%1,%2,%3}, {%4,%5,%6,%7}, {%8,%9}, {%0,%1,%2,%3};"
        : "+f"(d[0]), "+f"(d[1]), "+f"(d[2]), "+f"(d[3])
        : "r"(a[0]), "r"(a[1]), "r"(a[2]), "r"(a[3]), "r"(b[0]), "r"(b[1]));
}
__device__ __forceinline__ void ldsm4(uint32_t* r, uint32_t addr) {
    asm volatile("ldmatrix.sync.aligned.m8n8.x4.shared.b16 {%0,%1,%2,%3}, [%4];"
        : "=r"(r[0]), "=r"(r[1]), "=r"(r[2]), "=r"(r[3]) : "r"(addr));
}
__device__ __forceinline__ void cp16(uint32_t dst, const void* src) {
    asm volatile("cp.async.cg.shared.global [%0], [%1], 16;" :: "r"(dst), "l"(src));
}
#define CP_COMMIT() asm volatile("cp.async.commit_group;" ::: "memory")
#define CP_WAIT0()  asm volatile("cp.async.wait_group 0;" ::: "memory")
#define CP_WAIT1()  asm volatile("cp.async.wait_group 1;" ::: "memory")

__device__ __forceinline__ uint32_t pack_bf16x2(float lo, float hi) {
    __nv_bfloat162 p = __floats2bfloat162_rn(lo, hi);
    uint32_t u; memcpy(&u, &p, 4); return u;
}

// ---------------- kernel 0: merged init ----------------
__global__ __launch_bounds__(256) void k_init(
    const float* __restrict__ Wa, const float* __restrict__ Ws1,
    const float* __restrict__ bs1, const float* __restrict__ vn,
    float* __restrict__ out_u)
{
    const int bid = blockIdx.x;
    const int tid = threadIdx.x;
    if (bid < 1024) {
        int idx = bid * 256 + tid;
        if (idx < DU * DMODEL) {
            float v = Wa[idx];
            __nv_bfloat16 hi = __float2bfloat16(v);
            __nv_bfloat16 lo = __float2bfloat16(v - __bfloat162float(hi));
            g_Wa_hi[idx] = hi;
            g_Wa_lo[idx] = lo;
        }
        if (idx < HHID * DMODEL) {
            int h = idx >> 8, d = idx & 255;
            float v = Ws1[h * 512 + d];
            __nv_bfloat16 hi = __float2bfloat16(v);
            __nv_bfloat16 lo = __float2bfloat16(v - __bfloat162float(hi));
            g_W1_hi[idx] = hi;
            g_W1_lo[idx] = lo;
        }
        if (idx < BATCH * DU) out_u[idx] = 0.f;
        if (idx < BATCH) g_count[idx] = 0;
        if (idx == 0) { g_tile = 0; g_work = 0; }
    } else {
        int h = (bid - 1024) * 8 + (tid >> 5);
        int l = tid & 31;
        if (h >= HHID) return;
        const float* row = Ws1 + (size_t)h * 512 + 256;
        float s = 0.f;
#pragma unroll
        for (int d = l; d < 256; d += 32) s += row[d] * vn[d];
#pragma unroll
        for (int off = 16; off; off >>= 1) s += __shfl_xor_sync(0xffffffffu, s, off);
        if (l == 0) g_cvec[h] = s + bs1[h];
    }
}

// ---------------- kernel 1a: embedding + trig -> bf16 hi/lo ----------------
__global__ __launch_bounds__(256) void k_emb(
    const int* __restrict__ q_seq, const int* __restrict__ r_seq,
    const float* __restrict__ t_seq,
    const float* __restrict__ q_tab, const float* __restrict__ r_tab)
{
    __shared__ int sq[32], sr[32];
    __shared__ float st[32];
    const int tid = threadIdx.x;
    const int tok0 = blockIdx.x * 32;
    if (tid < 32) {
        sq[tid] = q_seq[tok0 + tid];
        sr[tid] = r_seq[tok0 + tid];
        st[tid] = t_seq[tok0 + tid];
    }
    __syncthreads();
    const int dp   = tid & 127;
    const int tseg = tid >> 7;
    const int d0   = dp * 2;
    const float KF = -9.2103403719761836f / 128.f;
    const float f0 = expf((float)(d0 & 127) * KF);
    const float f1 = expf((float)((d0 + 1) & 127) * KF);
    const bool  is_sin = d0 < 128;
    uint32_t* ghw = (uint32_t*)(g_hev_hi + (((size_t)tok0 + tseg * 16) << 8) + d0);
    uint32_t* glw = (uint32_t*)(g_hev_lo + (((size_t)tok0 + tseg * 16) << 8) + d0);
#pragma unroll 4
    for (int t = 0; t < 16; ++t) {
        int tok = tseg * 16 + t;
        float tv = st[tok];
        float a0 = tv * f0, a1 = tv * f1;
        float s0 = is_sin ? sinf(a0) : cosf(a0);
        float s1 = is_sin ? sinf(a1) : cosf(a1);
        const float2 q2 = *(const float2*)(q_tab + (size_t)sq[tok] * 256 + d0);
        const float2 r2 = *(const float2*)(r_tab + (size_t)sr[tok] * 256 + d0);
        float v0 = q2.x + r2.x + s0;
        float v1 = q2.y + r2.y + s1;
        float h0f = __bfloat162float(__float2bfloat16(v0));
        float h1f = __bfloat162float(__float2bfloat16(v1));
        ghw[(size_t)t << 7] = pack_bf16x2(h0f, h1f);
        glw[(size_t)t << 7] = pack_bf16x2(v0 - h0f, v1 - h1f);
    }
}

// ---------------- kernel 1b: pipelined HMMA logits (512 thr, reversed tiles) ----------------
#define LW_OFF   0
#define LW_TERM  67584
#define LH_OFF   135168
#define LH_BUF   34816
#define LH_TERM  17408
#define LSLOG    204800
#define LSTILE   205824
#define SMEM_LG  205952

__global__ __launch_bounds__(512, 1) void k_logits_mma(
    const float* __restrict__ mask, const float* __restrict__ Ws2,
    const float* __restrict__ bs2, float* __restrict__ outA)
{
    extern __shared__ char smem[];
    const uint32_t sb = smem_u32(smem);
    const int tid  = threadIdx.x;
    const int wid  = tid >> 5;
    const int lane = tid & 31;
    const int gid  = lane >> 2;
    const int warpM = wid >> 2;
    const int warpN = wid & 3;

    float* slog  = (float*)(smem + LSLOG);
    int*   stile = (int*)(smem + LSTILE);

    for (int i = tid; i < 8192; i += 512) {
        int term = i >> 12;
        int r = (i >> 5) & 127;
        int c = i & 31;
        const __nv_bfloat16* src = term ? g_W1_lo : g_W1_hi;
        uint4 v = ((const uint4*)(src + ((size_t)r << 8)))[c];
        *(uint4*)(smem + LW_OFF + term * LW_TERM + r * 528 + c * 16) = v;
    }

    float wc[2][2], cv[2][2];
#pragma unroll
    for (int m = 0; m < 2; ++m) {
        int h0 = warpM * 32 + m * 16 + gid;
        wc[m][0] = Ws2[h0];     wc[m][1] = Ws2[h0 + 8];
        cv[m][0] = g_cvec[h0];  cv[m][1] = g_cvec[h0 + 8];
    }
    const float b2v = bs2[0];

    const uint32_t w_ld = sb + LW_OFF + (uint32_t)((lane & 15) * 528 + (lane >> 4) * 16);
    const uint32_t h_ld = sb + LH_OFF +
        (uint32_t)((warpN * 16 + (lane & 15)) * 272 + (lane >> 4) * 16);

    if (tid == 0) *stile = atomicAdd(&g_tile, 1);
    __syncthreads();
    int tctr = *stile;
    int tile = NT2 - 1 - tctr;

    if (tctr < NT2) {
#pragma unroll
        for (int i = 0; i < 4; ++i) {
            int idx = tid + i * 512;
            int term = idx >> 10;
            int row  = (idx >> 4) & 63;
            int c    = idx & 15;
            const __nv_bfloat16* src = term ? g_hev_lo : g_hev_hi;
            cp16(sb + LH_OFF + (uint32_t)(term * LH_TERM + row * 272 + c * 16),
                 src + (((size_t)(tile * LTOK + row)) << 8) + (c << 3));
        }
        CP_COMMIT();
    }

    while (tctr < NT2) {
        const int tok0 = tile * LTOK;
        const int b    = tok0 >> 11;

#pragma unroll
        for (int i = 0; i < 4; ++i) {
            int idx = tid + i * 512;
            int term = idx >> 10;
            int row  = (idx >> 4) & 63;
            int c    = idx & 15;
            const __nv_bfloat16* src = term ? g_hev_lo : g_hev_hi;
            cp16(sb + LH_OFF + LH_BUF + (uint32_t)(term * LH_TERM + row * 272 + c * 16),
                 src + (((size_t)(tok0 + row)) << 8) + 128 + (c << 3));
        }
        CP_COMMIT();
        if (tid == 0) *stile = atomicAdd(&g_tile, 1);

        CP_WAIT1();
        __syncthreads();

        float C[2][2][4];
#pragma unroll
        for (int m = 0; m < 2; ++m)
#pragma unroll
            for (int n = 0; n < 2; ++n)
#pragma unroll
                for (int k = 0; k < 4; ++k) C[m][n][k] = 0.f;

#pragma unroll
        for (int ks = 0; ks < 8; ++ks) {
            uint32_t ah[2][4], al[2][4], bh[2][2], bl[2][2], tmp[4];
#pragma unroll
            for (int m = 0; m < 2; ++m) {
                uint32_t ro = (uint32_t)((warpM * 32 + m * 16) * 528 + ks * 32);
                ldsm4(ah[m], w_ld + ro);
                ldsm4(al[m], w_ld + LW_TERM + ro);
            }
            {
                uint32_t no = (uint32_t)(ks * 32);
                ldsm4(tmp, h_ld + no);
                bh[0][0] = tmp[0]; bh[1][0] = tmp[1];
                bh[0][1] = tmp[2]; bh[1][1] = tmp[3];
                ldsm4(tmp, h_ld + LH_TERM + no);
                bl[0][0] = tmp[0]; bl[1][0] = tmp[1];
                bl[0][1] = tmp[2]; bl[1][1] = tmp[3];
            }
#pragma unroll
            for (int m = 0; m < 2; ++m)
#pragma unroll
                for (int n = 0; n < 2; ++n) mma16816(C[m][n], ah[m], bh[n]);
#pragma unroll
            for (int m = 0; m < 2; ++m)
#pragma unroll
                for (int n = 0; n < 2; ++n) mma16816(C[m][n], ah[m], bl[n]);
#pragma unroll
            for (int m = 0; m < 2; ++m)
#pragma unroll
                for (int n = 0; n < 2; ++n) mma16816(C[m][n], al[m], bh[n]);
        }
        __syncthreads();

        const int nctr = *stile;
        const int ntile = NT2 - 1 - nctr;
        if (nctr < NT2) {
#pragma unroll
            for (int i = 0; i < 4; ++i) {
                int idx = tid + i * 512;
                int term = idx >> 10;
                int row  = (idx >> 4) & 63;
                int c    = idx & 15;
                const __nv_bfloat16* src = term ? g_hev_lo : g_hev_hi;
                cp16(sb + LH_OFF + (uint32_t)(term * LH_TERM + row * 272 + c * 16),
                     src + (((size_t)(ntile * LTOK + row)) << 8) + (c << 3));
            }
            CP_COMMIT();
            CP_WAIT1();
        } else {
            CP_WAIT0();
        }
        __syncthreads();

#pragma unroll
        for (int ks = 0; ks < 8; ++ks) {
            uint32_t ah[2][4], al[2][4], bh[2][2], bl[2][2], tmp[4];
#pragma unroll
            for (int m = 0; m < 2; ++m) {
                uint32_t ro = (uint32_t)((warpM * 32 + m * 16) * 528 + (8 + ks) * 32);
                ldsm4(ah[m], w_ld + ro);
                ldsm4(al[m], w_ld + LW_TERM + ro);
            }
            {
                uint32_t no = (uint32_t)(LH_BUF + ks * 32);
                ldsm4(tmp, h_ld + no);
                bh[0][0] = tmp[0]; bh[1][0] = tmp[1];
                bh[0][1] = tmp[2]; bh[1][1] = tmp[3];
                ldsm4(tmp, h_ld + LH_TERM + no);
                bl[0][0] = tmp[0]; bl[1][0] = tmp[1];
                bl[0][1] = tmp[2]; bl[1][1] = tmp[3];
            }
#pragma unroll
            for (int m = 0; m < 2; ++m)
#pragma unroll
                for (int n = 0; n < 2; ++n) mma16816(C[m][n], ah[m], bh[n]);
#pragma unroll
            for (int m = 0; m < 2; ++m)
#pragma unroll
                for (int n = 0; n < 2; ++n) mma16816(C[m][n], ah[m], bl[n]);
#pragma unroll
            for (int m = 0; m < 2; ++m)
#pragma unroll
                for (int n = 0; n < 2; ++n) mma16816(C[m][n], al[m], bh[n]);
        }

        {
            float tsum[2][2];
#pragma unroll
            for (int n = 0; n < 2; ++n) { tsum[n][0] = 0.f; tsum[n][1] = 0.f; }
#pragma unroll
            for (int m = 0; m < 2; ++m)
#pragma unroll
                for (int n = 0; n < 2; ++n) {
                    tsum[n][0] += wc[m][0] * lrelu(C[m][n][0] + cv[m][0])
                                + wc[m][1] * lrelu(C[m][n][2] + cv[m][1]);
                    tsum[n][1] += wc[m][0] * lrelu(C[m][n][1] + cv[m][0])
                                + wc[m][1] * lrelu(C[m][n][3] + cv[m][1]);
                }
#pragma unroll
            for (int n = 0; n < 2; ++n)
#pragma unroll
                for (int k2 = 0; k2 < 2; ++k2) {
                    float v = tsum[n][k2];
                    v += __shfl_xor_sync(0xffffffffu, v, 4);
                    v += __shfl_xor_sync(0xffffffffu, v, 8);
                    v += __shfl_xor_sync(0xffffffffu, v, 16);
                    tsum[n][k2] = v;
                }
            if (lane < 4) {
#pragma unroll
                for (int n = 0; n < 2; ++n) {
                    int t = warpN * 16 + n * 8 + 2 * lane;
                    slog[warpM * 64 + t]     = tsum[n][0];
                    slog[warpM * 64 + t + 1] = tsum[n][1];
                }
            }
        }
        __syncthreads();

        if (tid < 64) {
            float logit = slog[tid] + slog[64 + tid] + slog[128 + tid]
                        + slog[192 + tid] + b2v;
            float a = mask[tok0 + tid] / (1.f + expf(-logit * 100.f));
            outA[tok0 + tid]   = a;
            g_aval[tok0 + tid] = a;
            bool act = a > 1e-10f;
            unsigned mb = __ballot_sync(0xffffffffu, act);
            int cntw = __popc(mb);
            int base = 0;
            if (lane == 0 && cntw) base = atomicAdd(&g_count[b], cntw);
            base = __shfl_sync(0xffffffffu, base, 0);
            if (act) {
                int slot = base + __popc(mb & ((1u << lane) - 1u));
                g_active[b * LSEQ + slot] = (tok0 & (LSEQ - 1)) + tid;
            }
        }
        tctr = nctr;
        tile = ntile;
        __syncthreads();
    }
}

// ---------------- kernel 2: persistent dynamic HMMA aggregator ----------------
// 148 blocks x 512 thr; work items (ucol, b) via atomic counter; B restaged on ucol change.
// smem: B@0 (135168), A 2 bufs@135168 (69632), sa[2][64]@204800 (512),
//       stok[2][64]@205312 (512), swork@205824 — NO overlap (R13 bug fixed).
#define KA_B_OFF   0
#define KA_A_OFF   135168
#define KA_ABUF    34816
#define KA_ATERM   17408
#define KA_SA_OFF  204800
#define KA_STOK_OFF 205312
#define KA_SWORK   205824
#define SMEM_AGG   205952

__global__ __launch_bounds__(512, 1) void k_agg_p(const float* __restrict__ ba,
                                                  float* __restrict__ out_u)
{
    extern __shared__ char smem[];
    const uint32_t sb = smem_u32(smem);
    const int tid  = threadIdx.x;
    const int wid  = tid >> 5;
    const int lane = tid & 31;
    const int gid  = lane >> 2;
    const int warpM = wid >> 2;
    const int warpN = wid & 3;

    float* sa    = (float*)(smem + KA_SA_OFF);
    int*   stok  = (int*)(smem + KA_STOK_OFF);
    int*   swork = (int*)(smem + KA_SWORK);

    const uint32_t a_ld_base = sb + KA_A_OFF
        + (uint32_t)((lane & 15) * 272 + (lane >> 4) * 16);
    const uint32_t b_ld_base = sb + KA_B_OFF
        + (uint32_t)((warpN * 32 + (lane & 15)) * 528 + (lane >> 4) * 16);

    int cached_ucol = -1;
    float ban0[4], ban1[4];

    while (true) {
        if (tid == 0) *swork = atomicAdd(&g_work, 1);
        __syncthreads();
        const int w = *swork;
        if (w >= 512) break;
        const int ucol = w >> 6;     // 64-item runs share the u-chunk
        const int b    = w & 63;
        const int colbase = ucol * 128;

        if (ucol != cached_ucol) {
            __syncthreads();   // prior item's ldsm reads of B must complete
            for (int i = tid; i < 8192; i += 512) {
                int term = i >> 12;
                int r = (i >> 5) & 127;
                int c = i & 31;
                const __nv_bfloat16* src = term ? g_Wa_lo : g_Wa_hi;
                uint4 v = ((const uint4*)(src + ((size_t)(colbase + r) << 8)))[c];
                *(uint4*)(smem + KA_B_OFF + term * 67584 + r * 528 + c * 16) = v;
            }
#pragma unroll
            for (int n = 0; n < 4; ++n) {
                int c0 = colbase + warpN * 32 + n * 8 + 2 * (lane & 3);
                ban0[n] = ba[c0];
                ban1[n] = ba[c0 + 1];
            }
            cached_ucol = ucol;
        }

        const int cnt = g_count[b];
        const int ntile = (cnt + 63) >> 6;

        __syncthreads();   // B ready; protects stok/sa reuse across items

        float colacc[4][2];
#pragma unroll
        for (int n = 0; n < 4; ++n) { colacc[n][0] = 0.f; colacc[n][1] = 0.f; }

        if (tid < 64 && ntile > 0) {
            int tok = (tid < cnt) ? g_active[(b << 11) + tid] : 0;
            stok[tid] = tok;
            sa[tid]   = (tid < cnt) ? g_aval[(b << 11) + tok] : 0.f;
        }
        __syncthreads();

        if (ntile > 0) {
#pragma unroll
            for (int i = 0; i < 4; ++i) {
                int idx = tid + i * 512;
                int term = idx >> 10;
                int row  = (idx >> 4) & 63;
                int c    = idx & 15;
                const __nv_bfloat16* src = term ? g_hev_lo : g_hev_hi;
                cp16(sb + KA_A_OFF + (uint32_t)(term * KA_ATERM + row * 272 + c * 16),
                     src + (((size_t)(b << 11) + stok[row]) << 8) + (c << 3));
            }
            CP_COMMIT();
        }

        int cur = 0;
        for (int t = 0; t < ntile; ++t, cur ^= 1) {
            const int nxt = cur ^ 1;
            if (tid < 64 && t + 1 < ntile) {
                int slot = ((t + 1) << 6) + tid;
                int tok = (slot < cnt) ? g_active[(b << 11) + slot] : 0;
                stok[nxt * 64 + tid] = tok;
                sa[nxt * 64 + tid]   = (slot < cnt) ? g_aval[(b << 11) + tok] : 0.f;
            }
            CP_WAIT0();
            __syncthreads();

#pragma unroll
            for (int i = 0; i < 4; ++i) {
                int idx = tid + i * 512;
                int term = idx >> 10;
                int row  = (idx >> 4) & 63;
                int c    = idx & 15;
                const __nv_bfloat16* src = term ? g_hev_lo : g_hev_hi;
                cp16(sb + KA_A_OFF + KA_ABUF
                         + (uint32_t)(term * KA_ATERM + row * 272 + c * 16),
                     src + (((size_t)(b << 11) + stok[cur * 64 + row]) << 8) + 128 + (c << 3));
            }
            CP_COMMIT();

            float C[4][4];
#pragma unroll
            for (int n = 0; n < 4; ++n)
#pragma unroll
                for (int k = 0; k < 4; ++k) C[n][k] = 0.f;

#pragma unroll
            for (int ks = 0; ks < 8; ++ks) {
                uint32_t ah[4], al[4], bh[4][2], bl[4][2], tmp[4];
                {
                    uint32_t ro = (uint32_t)((warpM * 16) * 272 + ks * 32);
                    ldsm4(ah, a_ld_base + ro);
                    ldsm4(al, a_ld_base + KA_ATERM + ro);
                }
#pragma unroll
                for (int nc = 0; nc < 2; ++nc) {
                    uint32_t no = (uint32_t)(nc * 16 * 528 + ks * 32);
                    ldsm4(tmp, b_ld_base + no);
                    bh[2*nc][0] = tmp[0]; bh[2*nc+1][0] = tmp[1];
                    bh[2*nc][1] = tmp[2]; bh[2*nc+1][1] = tmp[3];
                    ldsm4(tmp, b_ld_base + 67584 + no);
                    bl[2*nc][0] = tmp[0]; bl[2*nc+1][0] = tmp[1];
                    bl[2*nc][1] = tmp[2]; bl[2*nc+1][1] = tmp[3];
                }
#pragma unroll
                for (int n = 0; n < 4; ++n) mma16816(C[n], ah, bh[n]);
#pragma unroll
                for (int n = 0; n < 4; ++n) mma16816(C[n], ah, bl[n]);
#pragma unroll
                for (int n = 0; n < 4; ++n) mma16816(C[n], al, bh[n]);
            }

            CP_WAIT0();
            __syncthreads();

            if (t + 1 < ntile) {
#pragma unroll
                for (int i = 0; i < 4; ++i) {
                    int idx = tid + i * 512;
                    int term = idx >> 10;
                    int row  = (idx >> 4) & 63;
                    int c    = idx & 15;
                    const __nv_bfloat16* src = term ? g_hev_lo : g_hev_hi;
                    cp16(sb + KA_A_OFF + (uint32_t)(term * KA_ATERM + row * 272 + c * 16),
                         src + (((size_t)(b << 11) + stok[nxt * 64 + row]) << 8) + (c << 3));
                }
                CP_COMMIT();
            }

#pragma unroll
            for (int ks = 0; ks < 8; ++ks) {
                uint32_t ah[4], al[4], bh[4][2], bl[4][2], tmp[4];
                {
                    uint32_t ro = (uint32_t)((warpM * 16) * 272 + ks * 32);
                    ldsm4(ah, a_ld_base + KA_ABUF + ro);
                    ldsm4(al, a_ld_base + KA_ABUF + KA_ATERM + ro);
                }
#pragma unroll
                for (int nc = 0; nc < 2; ++nc) {
                    uint32_t no = (uint32_t)(nc * 16 * 528 + 256 + ks * 32);
                    ldsm4(tmp, b_ld_base + no);
                    bh[2*nc][0] = tmp[0]; bh[2*nc+1][0] = tmp[1];
                    bh[2*nc][1] = tmp[2]; bh[2*nc+1][1] = tmp[3];
                    ldsm4(tmp, b_ld_base + 67584 + no);
                    bl[2*nc][0] = tmp[0]; bl[2*nc+1][0] = tmp[1];
                    bl[2*nc][1] = tmp[2]; bl[2*nc+1][1] = tmp[3];
                }
#pragma unroll
                for (int n = 0; n < 4; ++n) mma16816(C[n], ah, bh[n]);
#pragma unroll
                for (int n = 0; n < 4; ++n) mma16816(C[n], ah, bl[n]);
#pragma unroll
                for (int n = 0; n < 4; ++n) mma16816(C[n], al, bh[n]);
            }

            {
                float a0 = sa[cur * 64 + warpM * 16 + gid];
                float a1 = sa[cur * 64 + warpM * 16 + gid + 8];
#pragma unroll
                for (int n = 0; n < 4; ++n) {
                    colacc[n][0] += a0 * lrelu(C[n][0] + ban0[n])
                                  + a1 * lrelu(C[n][2] + ban0[n]);
                    colacc[n][1] += a0 * lrelu(C[n][1] + ban1[n])
                                  + a1 * lrelu(C[n][3] + ban1[n]);
                }
            }
        }

#pragma unroll
        for (int n = 0; n < 4; ++n)
#pragma unroll
            for (int j = 0; j < 2; ++j) {
                float v = colacc[n][j];
                v += __shfl_xor_sync(0xffffffffu, v, 4);
                v += __shfl_xor_sync(0xffffffffu, v, 8);
                v += __shfl_xor_sync(0xffffffffu, v, 16);
                colacc[n][j] = v;
            }
        if (lane < 4) {
#pragma unroll
            for (int n = 0; n < 4; ++n) {
                int c0 = colbase + warpN * 32 + n * 8 + 2 * lane;
                atomicAdd(&out_u[b * DU + c0],     colacc[n][0]);
                atomicAdd(&out_u[b * DU + c0 + 1], colacc[n][1]);
            }
        }
    }
}

// ---------------- launch ----------------
extern "C" void kernel_launch(void* const* d_in, const int* in_sizes, int n_in,
                              void* d_out, int out_size) {
    const int*   q_seq = (const int*)d_in[0];
    const int*   r_seq = (const int*)d_in[1];
    const float* t_seq = (const float*)d_in[2];
    const float* mask  = (const float*)d_in[3];
    const float* q_tab = (const float*)d_in[4];
    const float* r_tab = (const float*)d_in[5];
    const float* vn    = (const float*)d_in[6];
    const float* Ws1   = (const float*)d_in[7];
    const float* bs1   = (const float*)d_in[8];
    const float* Ws2   = (const float*)d_in[9];
    const float* bs2   = (const float*)d_in[10];
    const float* Wa    = (const float*)d_in[11];
    const float* ba    = (const float*)d_in[12];

    float* out_u = (float*)d_out;            // (64, 1024)
    float* outA  = out_u + BATCH * DU;       // (64, 2048)

    k_init<<<1040, 256>>>(Wa, Ws1, bs1, vn, out_u);

    k_emb<<<NTOK / 32, 256>>>(q_seq, r_seq, t_seq, q_tab, r_tab);

    cudaFuncSetAttribute(k_logits_mma, cudaFuncAttributeMaxDynamicSharedMemorySize, SMEM_LG);
    k_logits_mma<<<148, 512, SMEM_LG>>>(mask, Ws2, bs2, outA);

    cudaFuncSetAttribute(k_agg_p, cudaFuncAttributeMaxDynamicSharedMemorySize, SMEM_AGG);
    k_agg_p<<<148, 512, SMEM_AGG>>>(ba, out_u);
}

// round 16
// speedup vs baseline: 1.3377x; 1.0780x over previous
#include <cuda_runtime.h>
#include <cuda_bf16.h>
#include <math.h>
#include <stdint.h>

typedef unsigned long long ull;

#define BATCH 64
#define LSEQ  2048
#define DMODEL 256
#define DU 1024
#define HHID 128
#define NTOK (BATCH*LSEQ)
#define LTOK 64
#define NT2 (NTOK/LTOK)   // 2048

// ---------------- device scratch ----------------
__device__ __nv_bfloat16 g_hev_hi[(size_t)NTOK * DMODEL];
__device__ __nv_bfloat16 g_hev_lo[(size_t)NTOK * DMODEL];
__device__ __nv_bfloat16 g_Wa_hi[DU * DMODEL];
__device__ __nv_bfloat16 g_Wa_lo[DU * DMODEL];
__device__ __nv_bfloat16 g_W1_hi[HHID * DMODEL];
__device__ __nv_bfloat16 g_W1_lo[HHID * DMODEL];
__device__ float g_cvec[HHID];
__device__ float g_aval[NTOK];
__device__ int   g_active[NTOK];
__device__ int   g_count[BATCH];
__device__ int   g_tile;
__device__ int   g_work;

// ---------------- helpers ----------------
__device__ __forceinline__ float lrelu(float x) { return x > 0.f ? x : 0.2f * x; }

__device__ __forceinline__ uint32_t smem_u32(const void* p) {
    uint32_t a;
    asm("{ .reg .u64 t; cvta.to.shared.u64 t, %1; cvt.u32.u64 %0, t; }" : "=r"(a) : "l"(p));
    return a;
}
__device__ __forceinline__ void mma16816(float* d, const uint32_t* a, const uint32_t* b) {
    asm volatile(
        "mma.sync.aligned.m16n8k16.row.col.f32.bf16.bf16.f32 "
        "{%0,%1,%2,%3}, {%4,%5,%6,%7}, {%8,%9}, {%0,%1,%2,%3};"
        : "+f"(d[0]), "+f"(d[1]), "+f"(d[2]), "+f"(d[3])
        : "r"(a[0]), "r"(a[1]), "r"(a[2]), "r"(a[3]), "r"(b[0]), "r"(b[1]));
}
__device__ __forceinline__ void ldsm4(uint32_t* r, uint32_t addr) {
    asm volatile("ldmatrix.sync.aligned.m8n8.x4.shared.b16 {%0,%1,%2,%3}, [%4];"
        : "=r"(r[0]), "=r"(r[1]), "=r"(r[2]), "=r"(r[3]) : "r"(addr));
}
__device__ __forceinline__ void cp16(uint32_t dst, const void* src) {
    asm volatile("cp.async.cg.shared.global [%0], [%1], 16;" :: "r"(dst), "l"(src));
}
#define CP_COMMIT() asm volatile("cp.async.commit_group;" ::: "memory")
#define CP_WAIT0()  asm volatile("cp.async.wait_group 0;" ::: "memory")
#define CP_WAIT1()  asm volatile("cp.async.wait_group 1;" ::: "memory")

__device__ __forceinline__ uint32_t pack_bf16x2(float lo, float hi) {
    __nv_bfloat162 p = __floats2bfloat162_rn(lo, hi);
    uint32_t u; memcpy(&u, &p, 4); return u;
}

// ---------------- kernel 0: merged init ----------------
__global__ __launch_bounds__(256) void k_init(
    const float* __restrict__ Wa, const float* __restrict__ Ws1,
    const float* __restrict__ bs1, const float* __restrict__ vn,
    float* __restrict__ out_u)
{
    const int bid = blockIdx.x;
    const int tid = threadIdx.x;
    if (bid < 1024) {
        int idx = bid * 256 + tid;
        if (idx < DU * DMODEL) {
            float v = Wa[idx];
            __nv_bfloat16 hi = __float2bfloat16(v);
            __nv_bfloat16 lo = __float2bfloat16(v - __bfloat162float(hi));
            g_Wa_hi[idx] = hi;
            g_Wa_lo[idx] = lo;
        }
        if (idx < HHID * DMODEL) {
            int h = idx >> 8, d = idx & 255;
            float v = Ws1[h * 512 + d];
            __nv_bfloat16 hi = __float2bfloat16(v);
            __nv_bfloat16 lo = __float2bfloat16(v - __bfloat162float(hi));
            g_W1_hi[idx] = hi;
            g_W1_lo[idx] = lo;
        }
        if (idx < BATCH * DU) out_u[idx] = 0.f;
        if (idx < BATCH) g_count[idx] = 0;
        if (idx == 0) { g_tile = 0; g_work = 0; }
    } else {
        int h = (bid - 1024) * 8 + (tid >> 5);
        int l = tid & 31;
        if (h >= HHID) return;
        const float* row = Ws1 + (size_t)h * 512 + 256;
        float s = 0.f;
#pragma unroll
        for (int d = l; d < 256; d += 32) s += row[d] * vn[d];
#pragma unroll
        for (int off = 16; off; off >>= 1) s += __shfl_xor_sync(0xffffffffu, s, off);
        if (l == 0) g_cvec[h] = s + bs1[h];
    }
}

// ---------------- kernel 1a: embedding + sincos -> bf16 hi/lo ----------------
// Thread owns d-pair (d0,d0+1) AND (d0+128,d0+129): one sincosf per (token, d).
__global__ __launch_bounds__(256) void k_emb(
    const int* __restrict__ q_seq, const int* __restrict__ r_seq,
    const float* __restrict__ t_seq,
    const float* __restrict__ q_tab, const float* __restrict__ r_tab)
{
    __shared__ int sq[32], sr[32];
    __shared__ float st[32];
    const int tid = threadIdx.x;
    const int tok0 = blockIdx.x * 32;
    if (tid < 32) {
        sq[tid] = q_seq[tok0 + tid];
        sr[tid] = r_seq[tok0 + tid];
        st[tid] = t_seq[tok0 + tid];
    }
    __syncthreads();
    const int dp   = tid & 63;          // d-pair in sin half
    const int tseg = tid >> 6;          // 0..3 -> 8 tokens each
    const int d0   = dp * 2;            // 0..126
    const float KF = -9.2103403719761836f / 128.f;
    const float f0 = expf((float)d0 * KF);
    const float f1 = expf((float)(d0 + 1) * KF);
    uint32_t* ghw = (uint32_t*)(g_hev_hi + (((size_t)tok0 + tseg * 8) << 8) + d0);
    uint32_t* glw = (uint32_t*)(g_hev_lo + (((size_t)tok0 + tseg * 8) << 8) + d0);
#pragma unroll 2
    for (int t = 0; t < 8; ++t) {
        int tok = tseg * 8 + t;
        float tv = st[tok];
        float s0, c0, s1, c1;
        sincosf(tv * f0, &s0, &c0);
        sincosf(tv * f1, &s1, &c1);
        const float* qrow = q_tab + (size_t)sq[tok] * 256 + d0;
        const float* rrow = r_tab + (size_t)sr[tok] * 256 + d0;
        const float2 qa = *(const float2*)qrow;
        const float2 ra = *(const float2*)rrow;
        const float2 qb = *(const float2*)(qrow + 128);
        const float2 rb = *(const float2*)(rrow + 128);
        float v0 = qa.x + ra.x + s0;
        float v1 = qa.y + ra.y + s1;
        float v2 = qb.x + rb.x + c0;
        float v3 = qb.y + rb.y + c1;
        float h0f = __bfloat162float(__float2bfloat16(v0));
        float h1f = __bfloat162float(__float2bfloat16(v1));
        float h2f = __bfloat162float(__float2bfloat16(v2));
        float h3f = __bfloat162float(__float2bfloat16(v3));
        size_t off = (size_t)t << 7;   // t alone: base already includes tseg*8
        ghw[off]      = pack_bf16x2(h0f, h1f);
        ghw[off + 64] = pack_bf16x2(h2f, h3f);
        glw[off]      = pack_bf16x2(v0 - h0f, v1 - h1f);
        glw[off + 64] = pack_bf16x2(v2 - h2f, v3 - h3f);
    }
}

// ---------------- kernel 1b: pipelined HMMA logits (512 thr, reversed tiles) ----------------
#define LW_OFF   0
#define LW_TERM  67584
#define LH_OFF   135168
#define LH_BUF   34816
#define LH_TERM  17408
#define LSLOG    204800
#define LSTILE   205824
#define SMEM_LG  205952

__global__ __launch_bounds__(512, 1) void k_logits_mma(
    const float* __restrict__ mask, const float* __restrict__ Ws2,
    const float* __restrict__ bs2, float* __restrict__ outA)
{
    extern __shared__ char smem[];
    const uint32_t sb = smem_u32(smem);
    const int tid  = threadIdx.x;
    const int wid  = tid >> 5;
    const int lane = tid & 31;
    const int gid  = lane >> 2;
    const int warpM = wid >> 2;
    const int warpN = wid & 3;

    float* slog  = (float*)(smem + LSLOG);
    int*   stile = (int*)(smem + LSTILE);

    for (int i = tid; i < 8192; i += 512) {
        int term = i >> 12;
        int r = (i >> 5) & 127;
        int c = i & 31;
        const __nv_bfloat16* src = term ? g_W1_lo : g_W1_hi;
        uint4 v = ((const uint4*)(src + ((size_t)r << 8)))[c];
        *(uint4*)(smem + LW_OFF + term * LW_TERM + r * 528 + c * 16) = v;
    }

    float wc[2][2], cv[2][2];
#pragma unroll
    for (int m = 0; m < 2; ++m) {
        int h0 = warpM * 32 + m * 16 + gid;
        wc[m][0] = Ws2[h0];     wc[m][1] = Ws2[h0 + 8];
        cv[m][0] = g_cvec[h0];  cv[m][1] = g_cvec[h0 + 8];
    }
    const float b2v = bs2[0];

    const uint32_t w_ld = sb + LW_OFF + (uint32_t)((lane & 15) * 528 + (lane >> 4) * 16);
    const uint32_t h_ld = sb + LH_OFF +
        (uint32_t)((warpN * 16 + (lane & 15)) * 272 + (lane >> 4) * 16);

    if (tid == 0) *stile = atomicAdd(&g_tile, 1);
    __syncthreads();
    int tctr = *stile;
    int tile = NT2 - 1 - tctr;

    if (tctr < NT2) {
#pragma unroll
        for (int i = 0; i < 4; ++i) {
            int idx = tid + i * 512;
            int term = idx >> 10;
            int row  = (idx >> 4) & 63;
            int c    = idx & 15;
            const __nv_bfloat16* src = term ? g_hev_lo : g_hev_hi;
            cp16(sb + LH_OFF + (uint32_t)(term * LH_TERM + row * 272 + c * 16),
                 src + (((size_t)(tile * LTOK + row)) << 8) + (c << 3));
        }
        CP_COMMIT();
    }

    while (tctr < NT2) {
        const int tok0 = tile * LTOK;
        const int b    = tok0 >> 11;

#pragma unroll
        for (int i = 0; i < 4; ++i) {
            int idx = tid + i * 512;
            int term = idx >> 10;
            int row  = (idx >> 4) & 63;
            int c    = idx & 15;
            const __nv_bfloat16* src = term ? g_hev_lo : g_hev_hi;
            cp16(sb + LH_OFF + LH_BUF + (uint32_t)(term * LH_TERM + row * 272 + c * 16),
                 src + (((size_t)(tok0 + row)) << 8) + 128 + (c << 3));
        }
        CP_COMMIT();
        if (tid == 0) *stile = atomicAdd(&g_tile, 1);

        CP_WAIT1();
        __syncthreads();

        float C[2][2][4], D[2][2][4];
#pragma unroll
        for (int m = 0; m < 2; ++m)
#pragma unroll
            for (int n = 0; n < 2; ++n)
#pragma unroll
                for (int k = 0; k < 4; ++k) { C[m][n][k] = 0.f; D[m][n][k] = 0.f; }

#pragma unroll
        for (int ks = 0; ks < 8; ++ks) {
            uint32_t ah[2][4], al[2][4], bh[2][2], bl[2][2], tmp[4];
#pragma unroll
            for (int m = 0; m < 2; ++m) {
                uint32_t ro = (uint32_t)((warpM * 32 + m * 16) * 528 + ks * 32);
                ldsm4(ah[m], w_ld + ro);
                ldsm4(al[m], w_ld + LW_TERM + ro);
            }
            {
                uint32_t no = (uint32_t)(ks * 32);
                ldsm4(tmp, h_ld + no);
                bh[0][0] = tmp[0]; bh[1][0] = tmp[1];
                bh[0][1] = tmp[2]; bh[1][1] = tmp[3];
                ldsm4(tmp, h_ld + LH_TERM + no);
                bl[0][0] = tmp[0]; bl[1][0] = tmp[1];
                bl[0][1] = tmp[2]; bl[1][1] = tmp[3];
            }
#pragma unroll
            for (int m = 0; m < 2; ++m)
#pragma unroll
                for (int n = 0; n < 2; ++n) mma16816(C[m][n], ah[m], bh[n]);
#pragma unroll
            for (int m = 0; m < 2; ++m)
#pragma unroll
                for (int n = 0; n < 2; ++n) mma16816(D[m][n], ah[m], bl[n]);
#pragma unroll
            for (int m = 0; m < 2; ++m)
#pragma unroll
                for (int n = 0; n < 2; ++n) mma16816(C[m][n], al[m], bh[n]);
        }
        __syncthreads();

        const int nctr = *stile;
        const int ntile = NT2 - 1 - nctr;
        if (nctr < NT2) {
#pragma unroll
            for (int i = 0; i < 4; ++i) {
                int idx = tid + i * 512;
                int term = idx >> 10;
                int row  = (idx >> 4) & 63;
                int c    = idx & 15;
                const __nv_bfloat16* src = term ? g_hev_lo : g_hev_hi;
                cp16(sb + LH_OFF + (uint32_t)(term * LH_TERM + row * 272 + c * 16),
                     src + (((size_t)(ntile * LTOK + row)) << 8) + (c << 3));
            }
            CP_COMMIT();
            CP_WAIT1();
        } else {
            CP_WAIT0();
        }
        __syncthreads();

#pragma unroll
        for (int ks = 0; ks < 8; ++ks) {
            uint32_t ah[2][4], al[2][4], bh[2][2], bl[2][2], tmp[4];
#pragma unroll
            for (int m = 0; m < 2; ++m) {
                uint32_t ro = (uint32_t)((warpM * 32 + m * 16) * 528 + (8 + ks) * 32);
                ldsm4(ah[m], w_ld + ro);
                ldsm4(al[m], w_ld + LW_TERM + ro);
            }
            {
                uint32_t no = (uint32_t)(LH_BUF + ks * 32);
                ldsm4(tmp, h_ld + no);
                bh[0][0] = tmp[0]; bh[1][0] = tmp[1];
                bh[0][1] = tmp[2]; bh[1][1] = tmp[3];
                ldsm4(tmp, h_ld + LH_TERM + no);
                bl[0][0] = tmp[0]; bl[1][0] = tmp[1];
                bl[0][1] = tmp[2]; bl[1][1] = tmp[3];
            }
#pragma unroll
            for (int m = 0; m < 2; ++m)
#pragma unroll
                for (int n = 0; n < 2; ++n) mma16816(C[m][n], ah[m], bh[n]);
#pragma unroll
            for (int m = 0; m < 2; ++m)
#pragma unroll
                for (int n = 0; n < 2; ++n) mma16816(D[m][n], ah[m], bl[n]);
#pragma unroll
            for (int m = 0; m < 2; ++m)
#pragma unroll
                for (int n = 0; n < 2; ++n) mma16816(C[m][n], al[m], bh[n]);
        }

        {
            float tsum[2][2];
#pragma unroll
            for (int n = 0; n < 2; ++n) { tsum[n][0] = 0.f; tsum[n][1] = 0.f; }
#pragma unroll
            for (int m = 0; m < 2; ++m)
#pragma unroll
                for (int n = 0; n < 2; ++n) {
                    float e0 = C[m][n][0] + D[m][n][0];
                    float e1 = C[m][n][1] + D[m][n][1];
                    float e2 = C[m][n][2] + D[m][n][2];
                    float e3 = C[m][n][3] + D[m][n][3];
                    tsum[n][0] += wc[m][0] * lrelu(e0 + cv[m][0])
                                + wc[m][1] * lrelu(e2 + cv[m][1]);
                    tsum[n][1] += wc[m][0] * lrelu(e1 + cv[m][0])
                                + wc[m][1] * lrelu(e3 + cv[m][1]);
                }
#pragma unroll
            for (int n = 0; n < 2; ++n)
#pragma unroll
                for (int k2 = 0; k2 < 2; ++k2) {
                    float v = tsum[n][k2];
                    v += __shfl_xor_sync(0xffffffffu, v, 4);
                    v += __shfl_xor_sync(0xffffffffu, v, 8);
                    v += __shfl_xor_sync(0xffffffffu, v, 16);
                    tsum[n][k2] = v;
                }
            if (lane < 4) {
#pragma unroll
                for (int n = 0; n < 2; ++n) {
                    int t = warpN * 16 + n * 8 + 2 * lane;
                    slog[warpM * 64 + t]     = tsum[n][0];
                    slog[warpM * 64 + t + 1] = tsum[n][1];
                }
            }
        }
        __syncthreads();

        if (tid < 64) {
            float logit = slog[tid] + slog[64 + tid] + slog[128 + tid]
                        + slog[192 + tid] + b2v;
            float a = mask[tok0 + tid] / (1.f + expf(-logit * 100.f));
            outA[tok0 + tid]   = a;
            g_aval[tok0 + tid] = a;
            bool act = a > 1e-10f;
            unsigned mb = __ballot_sync(0xffffffffu, act);
            int cntw = __popc(mb);
            int base = 0;
            if (lane == 0 && cntw) base = atomicAdd(&g_count[b], cntw);
            base = __shfl_sync(0xffffffffu, base, 0);
            if (act) {
                int slot = base + __popc(mb & ((1u << lane) - 1u));
                g_active[b * LSEQ + slot] = (tok0 & (LSEQ - 1)) + tid;
            }
        }
        tctr = nctr;
        tile = ntile;
        __syncthreads();
    }
}

// ---------------- kernel 2: persistent dynamic HMMA aggregator ----------------
#define KA_B_OFF   0
#define KA_A_OFF   135168
#define KA_ABUF    34816
#define KA_ATERM   17408
#define KA_SA_OFF  204800
#define KA_STOK_OFF 205312
#define KA_SWORK   205824
#define SMEM_AGG   205952

__global__ __launch_bounds__(512, 1) void k_agg_p(const float* __restrict__ ba,
                                                  float* __restrict__ out_u)
{
    extern __shared__ char smem[];
    const uint32_t sb = smem_u32(smem);
    const int tid  = threadIdx.x;
    const int wid  = tid >> 5;
    const int lane = tid & 31;
    const int gid  = lane >> 2;
    const int warpM = wid >> 2;
    const int warpN = wid & 3;

    float* sa    = (float*)(smem + KA_SA_OFF);
    int*   stok  = (int*)(smem + KA_STOK_OFF);
    int*   swork = (int*)(smem + KA_SWORK);

    const uint32_t a_ld_base = sb + KA_A_OFF
        + (uint32_t)((lane & 15) * 272 + (lane >> 4) * 16);
    const uint32_t b_ld_base = sb + KA_B_OFF
        + (uint32_t)((warpN * 32 + (lane & 15)) * 528 + (lane >> 4) * 16);

    int cached_ucol = -1;
    float ban0[4], ban1[4];

    while (true) {
        if (tid == 0) *swork = atomicAdd(&g_work, 1);
        __syncthreads();
        const int w = *swork;
        if (w >= 512) break;
        const int ucol = w >> 6;
        const int b    = w & 63;
        const int colbase = ucol * 128;

        if (ucol != cached_ucol) {
            __syncthreads();
            for (int i = tid; i < 8192; i += 512) {
                int term = i >> 12;
                int r = (i >> 5) & 127;
                int c = i & 31;
                const __nv_bfloat16* src = term ? g_Wa_lo : g_Wa_hi;
                uint4 v = ((const uint4*)(src + ((size_t)(colbase + r) << 8)))[c];
                *(uint4*)(smem + KA_B_OFF + term * 67584 + r * 528 + c * 16) = v;
            }
#pragma unroll
            for (int n = 0; n < 4; ++n) {
                int c0 = colbase + warpN * 32 + n * 8 + 2 * (lane & 3);
                ban0[n] = ba[c0];
                ban1[n] = ba[c0 + 1];
            }
            cached_ucol = ucol;
        }

        const int cnt = g_count[b];
        const int ntile = (cnt + 63) >> 6;

        __syncthreads();

        float colacc[4][2];
#pragma unroll
        for (int n = 0; n < 4; ++n) { colacc[n][0] = 0.f; colacc[n][1] = 0.f; }

        if (tid < 64 && ntile > 0) {
            int tok = (tid < cnt) ? g_active[(b << 11) + tid] : 0;
            stok[tid] = tok;
            sa[tid]   = (tid < cnt) ? g_aval[(b << 11) + tok] : 0.f;
        }
        __syncthreads();

        if (ntile > 0) {
#pragma unroll
            for (int i = 0; i < 4; ++i) {
                int idx = tid + i * 512;
                int term = idx >> 10;
                int row  = (idx >> 4) & 63;
                int c    = idx & 15;
                const __nv_bfloat16* src = term ? g_hev_lo : g_hev_hi;
                cp16(sb + KA_A_OFF + (uint32_t)(term * KA_ATERM + row * 272 + c * 16),
                     src + (((size_t)(b << 11) + stok[row]) << 8) + (c << 3));
            }
            CP_COMMIT();
        }

        int cur = 0;
        for (int t = 0; t < ntile; ++t, cur ^= 1) {
            const int nxt = cur ^ 1;
            if (tid < 64 && t + 1 < ntile) {
                int slot = ((t + 1) << 6) + tid;
                int tok = (slot < cnt) ? g_active[(b << 11) + slot] : 0;
                stok[nxt * 64 + tid] = tok;
                sa[nxt * 64 + tid]   = (slot < cnt) ? g_aval[(b << 11) + tok] : 0.f;
            }
            CP_WAIT0();
            __syncthreads();

#pragma unroll
            for (int i = 0; i < 4; ++i) {
                int idx = tid + i * 512;
                int term = idx >> 10;
                int row  = (idx >> 4) & 63;
                int c    = idx & 15;
                const __nv_bfloat16* src = term ? g_hev_lo : g_hev_hi;
                cp16(sb + KA_A_OFF + KA_ABUF
                         + (uint32_t)(term * KA_ATERM + row * 272 + c * 16),
                     src + (((size_t)(b << 11) + stok[cur * 64 + row]) << 8) + 128 + (c << 3));
            }
            CP_COMMIT();

            float C[4][4], D[4][4];
#pragma unroll
            for (int n = 0; n < 4; ++n)
#pragma unroll
                for (int k = 0; k < 4; ++k) { C[n][k] = 0.f; D[n][k] = 0.f; }

#pragma unroll
            for (int ks = 0; ks < 8; ++ks) {
                uint32_t ah[4], al[4], bh[4][2], bl[4][2], tmp[4];
                {
                    uint32_t ro = (uint32_t)((warpM * 16) * 272 + ks * 32);
                    ldsm4(ah, a_ld_base + ro);
                    ldsm4(al, a_ld_base + KA_ATERM + ro);
                }
#pragma unroll
                for (int nc = 0; nc < 2; ++nc) {
                    uint32_t no = (uint32_t)(nc * 16 * 528 + ks * 32);
                    ldsm4(tmp, b_ld_base + no);
                    bh[2*nc][0] = tmp[0]; bh[2*nc+1][0] = tmp[1];
                    bh[2*nc][1] = tmp[2]; bh[2*nc+1][1] = tmp[3];
                    ldsm4(tmp, b_ld_base + 67584 + no);
                    bl[2*nc][0] = tmp[0]; bl[2*nc+1][0] = tmp[1];
                    bl[2*nc][1] = tmp[2]; bl[2*nc+1][1] = tmp[3];
                }
#pragma unroll
                for (int n = 0; n < 4; ++n) mma16816(C[n], ah, bh[n]);
#pragma unroll
                for (int n = 0; n < 4; ++n) mma16816(D[n], ah, bl[n]);
#pragma unroll
                for (int n = 0; n < 4; ++n) mma16816(C[n], al, bh[n]);
            }

            CP_WAIT0();
            __syncthreads();

            if (t + 1 < ntile) {
#pragma unroll
                for (int i = 0; i < 4; ++i) {
                    int idx = tid + i * 512;
                    int term = idx >> 10;
                    int row  = (idx >> 4) & 63;
                    int c    = idx & 15;
                    const __nv_bfloat16* src = term ? g_hev_lo : g_hev_hi;
                    cp16(sb + KA_A_OFF + (uint32_t)(term * KA_ATERM + row * 272 + c * 16),
                         src + (((size_t)(b << 11) + stok[nxt * 64 + row]) << 8) + (c << 3));
                }
                CP_COMMIT();
            }

#pragma unroll
            for (int ks = 0; ks < 8; ++ks) {
                uint32_t ah[4], al[4], bh[4][2], bl[4][2], tmp[4];
                {
                    uint32_t ro = (uint32_t)((warpM * 16) * 272 + ks * 32);
                    ldsm4(ah, a_ld_base + KA_ABUF + ro);
                    ldsm4(al, a_ld_base + KA_ABUF + KA_ATERM + ro);
                }
#pragma unroll
                for (int nc = 0; nc < 2; ++nc) {
                    uint32_t no = (uint32_t)(nc * 16 * 528 + 256 + ks * 32);
                    ldsm4(tmp, b_ld_base + no);
                    bh[2*nc][0] = tmp[0]; bh[2*nc+1][0] = tmp[1];
                    bh[2*nc][1] = tmp[2]; bh[2*nc+1][1] = tmp[3];
                    ldsm4(tmp, b_ld_base + 67584 + no);
                    bl[2*nc][0] = tmp[0]; bl[2*nc+1][0] = tmp[1];
                    bl[2*nc][1] = tmp[2]; bl[2*nc+1][1] = tmp[3];
                }
#pragma unroll
                for (int n = 0; n < 4; ++n) mma16816(C[n], ah, bh[n]);
#pragma unroll
                for (int n = 0; n < 4; ++n) mma16816(D[n], ah, bl[n]);
#pragma unroll
                for (int n = 0; n < 4; ++n) mma16816(C[n], al, bh[n]);
            }

            {
                float a0 = sa[cur * 64 + warpM * 16 + gid];
                float a1 = sa[cur * 64 + warpM * 16 + gid + 8];
#pragma unroll
                for (int n = 0; n < 4; ++n) {
                    float e0 = C[n][0] + D[n][0];
                    float e1 = C[n][1] + D[n][1];
                    float e2 = C[n][2] + D[n][2];
                    float e3 = C[n][3] + D[n][3];
                    colacc[n][0] += a0 * lrelu(e0 + ban0[n])
                                  + a1 * lrelu(e2 + ban0[n]);
                    colacc[n][1] += a0 * lrelu(e1 + ban1[n])
                                  + a1 * lrelu(e3 + ban1[n]);
                }
            }
        }

#pragma unroll
        for (int n = 0; n < 4; ++n)
#pragma unroll
            for (int j = 0; j < 2; ++j) {
                float v = colacc[n][j];
                v += __shfl_xor_sync(0xffffffffu, v, 4);
                v += __shfl_xor_sync(0xffffffffu, v, 8);
                v += __shfl_xor_sync(0xffffffffu, v, 16);
                colacc[n][j] = v;
            }
        if (lane < 4) {
#pragma unroll
            for (int n = 0; n < 4; ++n) {
                int c0 = colbase + warpN * 32 + n * 8 + 2 * lane;
                atomicAdd(&out_u[b * DU + c0],     colacc[n][0]);
                atomicAdd(&out_u[b * DU + c0 + 1], colacc[n][1]);
            }
        }
    }
}

// ---------------- launch ----------------
extern "C" void kernel_launch(void* const* d_in, const int* in_sizes, int n_in,
                              void* d_out, int out_size) {
    const int*   q_seq = (const int*)d_in[0];
    const int*   r_seq = (const int*)d_in[1];
    const float* t_seq = (const float*)d_in[2];
    const float* mask  = (const float*)d_in[3];
    const float* q_tab = (const float*)d_in[4];
    const float* r_tab = (const float*)d_in[5];
    const float* vn    = (const float*)d_in[6];
    const float* Ws1   = (const float*)d_in[7];
    const float* bs1   = (const float*)d_in[8];
    const float* Ws2   = (const float*)d_in[9];
    const float* bs2   = (const float*)d_in[10];
    const float* Wa    = (const float*)d_in[11];
    const float* ba    = (const float*)d_in[12];

    float* out_u = (float*)d_out;            // (64, 1024)
    float* outA  = out_u + BATCH * DU;       // (64, 2048)

    k_init<<<1040, 256>>>(Wa, Ws1, bs1, vn, out_u);

    k_emb<<<NTOK / 32, 256>>>(q_seq, r_seq, t_seq, q_tab, r_tab);

    cudaFuncSetAttribute(k_logits_mma, cudaFuncAttributeMaxDynamicSharedMemorySize, SMEM_LG);
    k_logits_mma<<<148, 512, SMEM_LG>>>(mask, Ws2, bs2, outA);

    cudaFuncSetAttribute(k_agg_p, cudaFuncAttributeMaxDynamicSharedMemorySize, SMEM_AGG);
    k_agg_p<<<148, 512, SMEM_AGG>>>(ba, out_u);
}